// round 2
// baseline (speedup 1.0000x reference)
#include <cuda_runtime.h>
#include <math.h>

// Problem shapes (fixed by the dataset)
#define B_SZ 4
#define T_SZ 4096
#define C_SZ 2048
#define M_SZ (B_SZ * T_SZ)   // 16384 rows
#define N_SZ (2 * C_SZ)      // 4096 output cols
#define K_SZ C_SZ            // 2048 reduction

// Scratch: gates and values, each [B*T, C] fp32 (128 MiB each).
__device__ float g_gate[(size_t)M_SZ * C_SZ];
__device__ float g_val [(size_t)M_SZ * C_SZ];

#define BM 128
#define BN 128
#define BK 8

// C = A * W^T (+bias), fused sigmoid/tanh epilogue.
// A: [M,K] row-major (x), W: [N,K] row-major. Both K-contiguous.
__global__ __launch_bounds__(256) void gemm_act_kernel(
    const float* __restrict__ A,
    const float* __restrict__ Wt,
    const float* __restrict__ bias)
{
    __shared__ float As[2][BK][BM];
    __shared__ float Bs[2][BK][BN];

    const int tid = threadIdx.x;
    const int bx  = blockIdx.x;   // N tile
    const int by  = blockIdx.y;   // M tile
    const int tx  = tid & 15;     // 0..15
    const int ty  = tid >> 4;     // 0..15

    // Global-load assignment: each thread loads one float4 of A and one of B per K-tile.
    const int lrow = tid >> 1;          // 0..127
    const int lcol = (tid & 1) * 4;     // 0 or 4
    const float* Aptr = A  + (size_t)(by * BM + lrow) * K_SZ + lcol;
    const float* Bptr = Wt + (size_t)(bx * BN + lrow) * K_SZ + lcol;

    float acc[8][8];
#pragma unroll
    for (int i = 0; i < 8; i++)
#pragma unroll
        for (int j = 0; j < 8; j++) acc[i][j] = 0.0f;

    // Preload tile 0
    {
        float4 a0 = *(const float4*)Aptr;
        float4 b0 = *(const float4*)Bptr;
        As[0][lcol + 0][lrow] = a0.x; As[0][lcol + 1][lrow] = a0.y;
        As[0][lcol + 2][lrow] = a0.z; As[0][lcol + 3][lrow] = a0.w;
        Bs[0][lcol + 0][lrow] = b0.x; Bs[0][lcol + 1][lrow] = b0.y;
        Bs[0][lcol + 2][lrow] = b0.z; Bs[0][lcol + 3][lrow] = b0.w;
    }
    __syncthreads();

    const int KT = K_SZ / BK;   // 256
    int buf = 0;

    for (int kt = 0; kt < KT; ++kt) {
        float4 a_reg, b_reg;
        const bool has_next = (kt + 1) < KT;
        if (has_next) {
            a_reg = *(const float4*)(Aptr + (size_t)(kt + 1) * BK);
            b_reg = *(const float4*)(Bptr + (size_t)(kt + 1) * BK);
        }

#pragma unroll
        for (int k = 0; k < BK; ++k) {
            float a[8], b[8];
            *(float4*)&a[0] = *(const float4*)&As[buf][k][ty * 4];
            *(float4*)&a[4] = *(const float4*)&As[buf][k][64 + ty * 4];
            *(float4*)&b[0] = *(const float4*)&Bs[buf][k][tx * 4];
            *(float4*)&b[4] = *(const float4*)&Bs[buf][k][64 + tx * 4];
#pragma unroll
            for (int i = 0; i < 8; i++)
#pragma unroll
                for (int j = 0; j < 8; j++)
                    acc[i][j] = fmaf(a[i], b[j], acc[i][j]);
        }

        if (has_next) {
            const int nb = buf ^ 1;
            As[nb][lcol + 0][lrow] = a_reg.x; As[nb][lcol + 1][lrow] = a_reg.y;
            As[nb][lcol + 2][lrow] = a_reg.z; As[nb][lcol + 3][lrow] = a_reg.w;
            Bs[nb][lcol + 0][lrow] = b_reg.x; Bs[nb][lcol + 1][lrow] = b_reg.y;
            Bs[nb][lcol + 2][lrow] = b_reg.z; Bs[nb][lcol + 3][lrow] = b_reg.w;
            __syncthreads();
            buf = nb;
        }
    }

    // Epilogue: bias + activation, write gates/values to scratch.
    int rows[8], cols[8];
#pragma unroll
    for (int i = 0; i < 4; i++) {
        rows[i]     = by * BM + ty * 4 + i;
        rows[i + 4] = by * BM + 64 + ty * 4 + i;
        cols[i]     = bx * BN + tx * 4 + i;
        cols[i + 4] = bx * BN + 64 + tx * 4 + i;
    }
    float bv[8];
#pragma unroll
    for (int j = 0; j < 8; j++) bv[j] = bias[cols[j]];

    // BN=128 divides C=2048, so a block is entirely gates or entirely values.
    const bool is_gate = (bx * BN) < C_SZ;
    float* dst        = is_gate ? g_gate : g_val;
    const int coff    = is_gate ? 0 : C_SZ;

#pragma unroll
    for (int i = 0; i < 8; i++) {
        const size_t rbase = (size_t)rows[i] * C_SZ;
#pragma unroll
        for (int j = 0; j < 8; j++) {
            float v = acc[i][j] + bv[j];
            float r = is_gate ? (1.0f / (1.0f + expf(-v))) : tanhf(v);
            dst[rbase + (cols[j] - coff)] = r;
        }
    }
}

// Sequential scan over T per (b, c) sequence. 8192 threads, coalesced across c.
// h_t = g_t * h_{t-1} + v_t,  h_{-1} = 0.
#define SCAN_U 16
__global__ __launch_bounds__(128) void scan_kernel(float* __restrict__ out)
{
    const int s = blockIdx.x * blockDim.x + threadIdx.x;
    if (s >= B_SZ * C_SZ) return;
    const int bb = s / C_SZ;
    const int c  = s - bb * C_SZ;
    const size_t base = (size_t)bb * T_SZ * C_SZ + c;

    const float* gp = g_gate + base;
    const float* vp = g_val  + base;
    float*       op = out    + base;

    float h = 0.0f;
    for (int t = 0; t < T_SZ; t += SCAN_U) {
        float g[SCAN_U], v[SCAN_U];
#pragma unroll
        for (int u = 0; u < SCAN_U; u++) {
            g[u] = __ldg(gp + (size_t)(t + u) * C_SZ);
            v[u] = __ldg(vp + (size_t)(t + u) * C_SZ);
        }
#pragma unroll
        for (int u = 0; u < SCAN_U; u++) {
            h = fmaf(g[u], h, v[u]);
            op[(size_t)(t + u) * C_SZ] = h;
        }
    }
}

extern "C" void kernel_launch(void* const* d_in, const int* in_sizes, int n_in,
                              void* d_out, int out_size)
{
    const float* x  = (const float*)d_in[0];  // [B,T,C]
    const float* W  = (const float*)d_in[1];  // [2C,C]
    const float* bi = (const float*)d_in[2];  // [2C]
    float* out = (float*)d_out;               // [B,T,C]

    dim3 grid(N_SZ / BN, M_SZ / BM);          // (32, 128)
    gemm_act_kernel<<<grid, 256>>>(x, W, bi);

    const int nseq = B_SZ * C_SZ;             // 8192
    scan_kernel<<<(nseq + 127) / 128, 128>>>(out);
}

// round 4
// speedup vs baseline: 1.7601x; 1.7601x over previous
#include <cuda_runtime.h>
#include <cuda_bf16.h>
#include <cstdint>
#include <math.h>

// ---------------- problem shapes ----------------
#define B_SZ 4
#define T_SZ 4096
#define C_SZ 2048
#define M_SZ (B_SZ * T_SZ)   // 16384
#define N_SZ (2 * C_SZ)      // 4096
#define K_SZ C_SZ            // 2048

// ---------------- device scratch ----------------
__device__ float g_gate[(size_t)M_SZ * C_SZ];
__device__ float g_val [(size_t)M_SZ * C_SZ];
__device__ __nv_bfloat16 g_ahi[(size_t)M_SZ * K_SZ];
__device__ __nv_bfloat16 g_alo[(size_t)M_SZ * K_SZ];
__device__ __nv_bfloat16 g_bhi[(size_t)N_SZ * K_SZ];
__device__ __nv_bfloat16 g_blo[(size_t)N_SZ * K_SZ];

// ---------------- helpers ----------------
__device__ __forceinline__ uint32_t smem_u32(const void* p) {
    uint32_t a;
    asm("{ .reg .u64 t; cvta.to.shared.u64 t, %1; cvt.u32.u64 %0, t; }" : "=r"(a) : "l"(p));
    return a;
}
__device__ __forceinline__ void cp16(uint32_t dst, const void* src) {
    asm volatile("cp.async.cg.shared.global [%0], [%1], 16;" :: "r"(dst), "l"(src));
}
#define CP_COMMIT() asm volatile("cp.async.commit_group;" ::: "memory")
#define CP_WAIT0()  asm volatile("cp.async.wait_group 0;" ::: "memory")
#define CP_WAIT1()  asm volatile("cp.async.wait_group 1;" ::: "memory")

#define LDSM4(r0, r1, r2, r3, addr) \
    asm volatile("ldmatrix.sync.aligned.m8n8.x4.shared.b16 {%0,%1,%2,%3}, [%4];" \
        : "=r"(r0), "=r"(r1), "=r"(r2), "=r"(r3) : "r"(addr))

#define MMA16816(d, a, b0, b1) \
    asm volatile("mma.sync.aligned.m16n8k16.row.col.f32.bf16.bf16.f32 " \
        "{%0,%1,%2,%3},{%4,%5,%6,%7},{%8,%9},{%0,%1,%2,%3};" \
        : "+f"((d)[0]), "+f"((d)[1]), "+f"((d)[2]), "+f"((d)[3]) \
        : "r"((a)[0]), "r"((a)[1]), "r"((a)[2]), "r"((a)[3]), "r"(b0), "r"(b1))

__device__ __forceinline__ float act_sig(float v)  { return 1.0f / (1.0f + __expf(-v)); }
__device__ __forceinline__ float act_tanh(float v) { return 1.0f - 2.0f / (__expf(2.0f * v) + 1.0f); }

// ---------------- convert: fp32 -> bf16 hi/lo split ----------------
__global__ __launch_bounds__(256) void convert_kernel(
    const float* __restrict__ x, const float* __restrict__ W)
{
    const size_t MK4 = (size_t)M_SZ * K_SZ / 4;
    const size_t NK4 = (size_t)N_SZ * K_SZ / 4;
    size_t i = (size_t)blockIdx.x * blockDim.x + threadIdx.x;
    if (i >= MK4 + NK4) return;

    const float4* src; ushort4* hi; ushort4* lo; size_t j;
    if (i < MK4) { src = (const float4*)x; hi = (ushort4*)g_ahi; lo = (ushort4*)g_alo; j = i; }
    else { src = (const float4*)W; hi = (ushort4*)g_bhi; lo = (ushort4*)g_blo; j = i - MK4; }

    float4 v = src[j];
    float vv[4] = {v.x, v.y, v.z, v.w};
    unsigned short hs[4], ls[4];
#pragma unroll
    for (int u = 0; u < 4; u++) {
        __nv_bfloat16 hb = __float2bfloat16_rn(vv[u]);
        float r = vv[u] - __bfloat162float(hb);
        __nv_bfloat16 lb = __float2bfloat16_rn(r);
        hs[u] = __bfloat16_as_ushort(hb);
        ls[u] = __bfloat16_as_ushort(lb);
    }
    ushort4 h, l;
    h.x = hs[0]; h.y = hs[1]; h.z = hs[2]; h.w = hs[3];
    l.x = ls[0]; l.y = ls[1]; l.z = ls[2]; l.w = ls[3];
    hi[j] = h; lo[j] = l;
}

// ---------------- HMMA GEMM: C = A * W^T (+bias), fused activation ----------------
// CTA tile 128x128, BK=32. 8 warps: 2(M) x 4(N), warp tile 64x32.
// smem per stage: 4 tiles (Ah, Al, Bh, Bl), each 128 rows x 32 bf16, row stride 80B.
#define LDSM_STRIDE 80
#define TILE_SM 10240            // 128 * 80
#define STAGE_SM (4 * TILE_SM)   // 40960
#define GEMM_SMEM (2 * STAGE_SM) // 81920
#define KCHUNKS 64               // 2048 / 32

__global__ __launch_bounds__(256) void gemm_mma(const float* __restrict__ bias)
{
    extern __shared__ char smem[];
    const uint32_t sb = smem_u32(smem);
    const int tid  = threadIdx.x;
    const int lane = tid & 31;
    const int wid  = tid >> 5;
    const int bx = blockIdx.x;   // N tile 0..31
    const int by = blockIdx.y;   // M tile 0..127

    const int m_off = (wid & 1) * 64;
    const int n_off = (wid >> 1) * 32;

    float acc[4][4][4];
#pragma unroll
    for (int mi = 0; mi < 4; mi++)
#pragma unroll
        for (int ni = 0; ni < 4; ni++)
#pragma unroll
            for (int u = 0; u < 4; u++) acc[mi][ni][u] = 0.0f;

    // ldmatrix per-lane address components
    const uint32_t a_off = (uint32_t)(m_off + (lane & 15)) * LDSM_STRIDE + ((lane >> 4) * 16);
    const uint32_t b_off = (uint32_t)(n_off + (lane & 7) + (((lane >> 3) >> 1) * 8)) * LDSM_STRIDE
                           + (((lane >> 3) & 1) * 16);

    // cp.async mapping: per tile, thread does ops o = 2*tid, 2*tid+1; row = o>>2, seg = o&3
    const int o0   = 2 * tid;
    const int rowL = o0 >> 2;            // 0..127
    const int segL = o0 & 3;             // 0 or 2 (i adds 0/1)

    // ---- loader ----
    auto load_stage = [&](int st, int c) {
        const uint32_t base = sb + st * STAGE_SM;
#pragma unroll
        for (int i = 0; i < 2; i++) {
            const int row = rowL;            // both ops same row (segs consecutive)
            const int seg = segL + i;
            const size_t gA = (size_t)(by * 128 + row) * K_SZ + c * 32 + seg * 8;
            const size_t gB = (size_t)(bx * 128 + row) * K_SZ + c * 32 + seg * 8;
            const uint32_t so = base + (uint32_t)row * LDSM_STRIDE + seg * 16;
            cp16(so,               g_ahi + gA);
            cp16(so +     TILE_SM, g_alo + gA);
            cp16(so + 2 * TILE_SM, g_bhi + gB);
            cp16(so + 3 * TILE_SM, g_blo + gB);
        }
    };

    // ---- compute one chunk from stage st ----
    auto compute = [&](int st) {
        const uint32_t base = sb + st * STAGE_SM;
#pragma unroll
        for (int s = 0; s < 2; s++) {
            const uint32_t ks = s * 32;                 // 16 bf16 = 32B per k16 step
            const uint32_t aB = base + a_off + ks;                 // Ah tile
            const uint32_t bB = base + 2 * TILE_SM + b_off + ks;   // Bh tile
            uint32_t a[16], bh[8], bl[8];
#pragma unroll
            for (int mi = 0; mi < 4; mi++)
                LDSM4(a[mi*4+0], a[mi*4+1], a[mi*4+2], a[mi*4+3], aB + mi * 16 * LDSM_STRIDE);
#pragma unroll
            for (int nj = 0; nj < 2; nj++)
                LDSM4(bh[nj*4+0], bh[nj*4+1], bh[nj*4+2], bh[nj*4+3], bB + nj * 16 * LDSM_STRIDE);
            // pass 1: Ah * Bh
#pragma unroll
            for (int mi = 0; mi < 4; mi++)
#pragma unroll
                for (int ni = 0; ni < 4; ni++)
                    MMA16816(acc[mi][ni], &a[mi*4], bh[(ni>>1)*4 + (ni&1)*2], bh[(ni>>1)*4 + (ni&1)*2 + 1]);
            // pass 2: Ah * Bl
#pragma unroll
            for (int nj = 0; nj < 2; nj++)
                LDSM4(bl[nj*4+0], bl[nj*4+1], bl[nj*4+2], bl[nj*4+3], bB + TILE_SM + nj * 16 * LDSM_STRIDE);
#pragma unroll
            for (int mi = 0; mi < 4; mi++)
#pragma unroll
                for (int ni = 0; ni < 4; ni++)
                    MMA16816(acc[mi][ni], &a[mi*4], bl[(ni>>1)*4 + (ni&1)*2], bl[(ni>>1)*4 + (ni&1)*2 + 1]);
            // pass 3: Al * Bh
#pragma unroll
            for (int mi = 0; mi < 4; mi++)
                LDSM4(a[mi*4+0], a[mi*4+1], a[mi*4+2], a[mi*4+3], aB + TILE_SM + mi * 16 * LDSM_STRIDE);
#pragma unroll
            for (int mi = 0; mi < 4; mi++)
#pragma unroll
                for (int ni = 0; ni < 4; ni++)
                    MMA16816(acc[mi][ni], &a[mi*4], bh[(ni>>1)*4 + (ni&1)*2], bh[(ni>>1)*4 + (ni&1)*2 + 1]);
        }
    };

    // ---- pipelined main loop ----
    load_stage(0, 0); CP_COMMIT();
    for (int c = 0; c < KCHUNKS; c++) {
        if (c + 1 < KCHUNKS) {
            load_stage((c + 1) & 1, c + 1); CP_COMMIT();
            CP_WAIT1();
        } else {
            CP_WAIT0();
        }
        __syncthreads();
        compute(c & 1);
        __syncthreads();
    }

    // ---- epilogue: bias + activation -> g_gate / g_val ----
    const int n0 = bx * 128;
    const bool is_gate = (bx < 16);
    float* dst = is_gate ? g_gate : g_val;
    const int cadj = is_gate ? 0 : C_SZ;
    const int r_in  = lane >> 2;
    const int cpair = (lane & 3) * 2;

#pragma unroll
    for (int mi = 0; mi < 4; mi++) {
        const int gm = by * 128 + m_off + mi * 16 + r_in;
        float* row0 = dst + (size_t)gm * C_SZ + (n0 - cadj);
        float* row1 = row0 + (size_t)8 * C_SZ;
#pragma unroll
        for (int ni = 0; ni < 4; ni++) {
            const int col = n_off + ni * 8 + cpair;
            const float b0 = __ldg(bias + n0 + col);
            const float b1 = __ldg(bias + n0 + col + 1);
            float v0 = acc[mi][ni][0] + b0, v1 = acc[mi][ni][1] + b1;
            float v2 = acc[mi][ni][2] + b0, v3 = acc[mi][ni][3] + b1;
            float o0, o1, o2, o3;
            if (is_gate) { o0 = act_sig(v0);  o1 = act_sig(v1);  o2 = act_sig(v2);  o3 = act_sig(v3); }
            else         { o0 = act_tanh(v0); o1 = act_tanh(v1); o2 = act_tanh(v2); o3 = act_tanh(v3); }
            *(float2*)(row0 + col) = make_float2(o0, o1);
            *(float2*)(row1 + col) = make_float2(o2, o3);
        }
    }
}

// ---------------- scan (unchanged) ----------------
#define SCAN_U 16
__global__ __launch_bounds__(128) void scan_kernel(float* __restrict__ out)
{
    const int s = blockIdx.x * blockDim.x + threadIdx.x;
    if (s >= B_SZ * C_SZ) return;
    const int bb = s / C_SZ;
    const int c  = s - bb * C_SZ;
    const size_t base = (size_t)bb * T_SZ * C_SZ + c;

    const float* gp = g_gate + base;
    const float* vp = g_val  + base;
    float*       op = out    + base;

    float h = 0.0f;
    for (int t = 0; t < T_SZ; t += SCAN_U) {
        float g[SCAN_U], v[SCAN_U];
#pragma unroll
        for (int u = 0; u < SCAN_U; u++) {
            g[u] = __ldg(gp + (size_t)(t + u) * C_SZ);
            v[u] = __ldg(vp + (size_t)(t + u) * C_SZ);
        }
#pragma unroll
        for (int u = 0; u < SCAN_U; u++) {
            h = fmaf(g[u], h, v[u]);
            op[(size_t)(t + u) * C_SZ] = h;
        }
    }
}

// ---------------- launch ----------------
extern "C" void kernel_launch(void* const* d_in, const int* in_sizes, int n_in,
                              void* d_out, int out_size)
{
    const float* x  = (const float*)d_in[0];  // [B,T,C]
    const float* W  = (const float*)d_in[1];  // [2C,C]
    const float* bi = (const float*)d_in[2];  // [2C]
    float* out = (float*)d_out;               // [B,T,C]

    cudaFuncSetAttribute(gemm_mma, cudaFuncAttributeMaxDynamicSharedMemorySize, GEMM_SMEM);

    const size_t total4 = ((size_t)M_SZ * K_SZ + (size_t)N_SZ * K_SZ) / 4;
    convert_kernel<<<(unsigned)((total4 + 255) / 256), 256>>>(x, W);

    gemm_mma<<<dim3(32, 128), 256, GEMM_SMEM>>>(bi);

    scan_kernel<<<(B_SZ * C_SZ + 127) / 128, 128>>>(out);
}

// round 5
// speedup vs baseline: 1.7659x; 1.0033x over previous
#include <cuda_runtime.h>
#include <cuda_bf16.h>
#include <cstdint>
#include <math.h>

// ---------------- problem shapes ----------------
#define B_SZ 4
#define T_SZ 4096
#define C_SZ 2048
#define M_SZ (B_SZ * T_SZ)   // 16384
#define N_SZ (2 * C_SZ)      // 4096
#define K_SZ C_SZ            // 2048

// ---------------- device scratch ----------------
__device__ float g_gate[(size_t)M_SZ * C_SZ];
__device__ float g_val [(size_t)M_SZ * C_SZ];
__device__ __nv_bfloat16 g_ahi[(size_t)M_SZ * K_SZ];
__device__ __nv_bfloat16 g_alo[(size_t)M_SZ * K_SZ];
__device__ __nv_bfloat16 g_bhi[(size_t)N_SZ * K_SZ];
__device__ __nv_bfloat16 g_blo[(size_t)N_SZ * K_SZ];

// ---------------- helpers ----------------
__device__ __forceinline__ uint32_t smem_u32(const void* p) {
    uint32_t a;
    asm("{ .reg .u64 t; cvta.to.shared.u64 t, %1; cvt.u32.u64 %0, t; }" : "=r"(a) : "l"(p));
    return a;
}
__device__ __forceinline__ void cp16(uint32_t dst, const void* src) {
    asm volatile("cp.async.cg.shared.global [%0], [%1], 16;" :: "r"(dst), "l"(src));
}
#define CP_COMMIT() asm volatile("cp.async.commit_group;" ::: "memory")
#define CP_WAIT0()  asm volatile("cp.async.wait_group 0;" ::: "memory")
#define CP_WAIT1()  asm volatile("cp.async.wait_group 1;" ::: "memory")

#define LDSM4(r0, r1, r2, r3, addr) \
    asm volatile("ldmatrix.sync.aligned.m8n8.x4.shared.b16 {%0,%1,%2,%3}, [%4];" \
        : "=r"(r0), "=r"(r1), "=r"(r2), "=r"(r3) : "r"(addr))

#define MMA16816(d, a, b0, b1) \
    asm volatile("mma.sync.aligned.m16n8k16.row.col.f32.bf16.bf16.f32 " \
        "{%0,%1,%2,%3},{%4,%5,%6,%7},{%8,%9},{%0,%1,%2,%3};" \
        : "+f"((d)[0]), "+f"((d)[1]), "+f"((d)[2]), "+f"((d)[3]) \
        : "r"((a)[0]), "r"((a)[1]), "r"((a)[2]), "r"((a)[3]), "r"(b0), "r"(b1))

__device__ __forceinline__ float act_sig(float v)  { return 1.0f / (1.0f + __expf(-v)); }
__device__ __forceinline__ float act_tanh(float v) { return 1.0f - 2.0f / (__expf(2.0f * v) + 1.0f); }

// ---------------- convert: fp32 -> bf16 hi/lo split ----------------
__global__ __launch_bounds__(256) void convert_kernel(
    const float* __restrict__ x, const float* __restrict__ W)
{
    const size_t MK4 = (size_t)M_SZ * K_SZ / 4;
    const size_t NK4 = (size_t)N_SZ * K_SZ / 4;
    size_t i = (size_t)blockIdx.x * blockDim.x + threadIdx.x;
    if (i >= MK4 + NK4) return;

    const float4* src; ushort4* hi; ushort4* lo; size_t j;
    if (i < MK4) { src = (const float4*)x; hi = (ushort4*)g_ahi; lo = (ushort4*)g_alo; j = i; }
    else { src = (const float4*)W; hi = (ushort4*)g_bhi; lo = (ushort4*)g_blo; j = i - MK4; }

    float4 v = src[j];
    float vv[4] = {v.x, v.y, v.z, v.w};
    unsigned short hs[4], ls[4];
#pragma unroll
    for (int u = 0; u < 4; u++) {
        __nv_bfloat16 hb = __float2bfloat16_rn(vv[u]);
        float r = vv[u] - __bfloat162float(hb);
        __nv_bfloat16 lb = __float2bfloat16_rn(r);
        hs[u] = __bfloat16_as_ushort(hb);
        ls[u] = __bfloat16_as_ushort(lb);
    }
    ushort4 h, l;
    h.x = hs[0]; h.y = hs[1]; h.z = hs[2]; h.w = hs[3];
    l.x = ls[0]; l.y = ls[1]; l.z = ls[2]; l.w = ls[3];
    hi[j] = h; lo[j] = l;
}

// ---------------- HMMA GEMM: C = A * W^T (+bias), fused activation ----------------
// CTA tile 128x128, BK=32. 8 warps: 2(M) x 4(N), warp tile 64x32.
// smem per stage: 4 tiles (Ah, Al, Bh, Bl), each 128 rows x 32 bf16, row stride 80B.
#define LDSM_STRIDE 80
#define TILE_SM 10240            // 128 * 80
#define STAGE_SM (4 * TILE_SM)   // 40960
#define GEMM_SMEM (2 * STAGE_SM) // 81920
#define KCHUNKS 64               // 2048 / 32

__global__ __launch_bounds__(256) void gemm_mma(const float* __restrict__ bias)
{
    extern __shared__ char smem[];
    const uint32_t sb = smem_u32(smem);
    const int tid  = threadIdx.x;
    const int lane = tid & 31;
    const int wid  = tid >> 5;
    const int bx = blockIdx.x;   // N tile 0..31
    const int by = blockIdx.y;   // M tile 0..127

    const int m_off = (wid & 1) * 64;
    const int n_off = (wid >> 1) * 32;

    float acc[4][4][4];
#pragma unroll
    for (int mi = 0; mi < 4; mi++)
#pragma unroll
        for (int ni = 0; ni < 4; ni++)
#pragma unroll
            for (int u = 0; u < 4; u++) acc[mi][ni][u] = 0.0f;

    // ldmatrix per-lane address components
    const uint32_t a_off = (uint32_t)(m_off + (lane & 15)) * LDSM_STRIDE + ((lane >> 4) * 16);
    const uint32_t b_off = (uint32_t)(n_off + (lane & 7) + (((lane >> 3) >> 1) * 8)) * LDSM_STRIDE
                           + (((lane >> 3) & 1) * 16);

    // cp.async mapping: per tile, thread does ops o = 2*tid, 2*tid+1; row = o>>2, seg = o&3
    const int o0   = 2 * tid;
    const int rowL = o0 >> 2;            // 0..127
    const int segL = o0 & 3;             // 0 or 2 (i adds 0/1)

    // ---- loader ----
    auto load_stage = [&](int st, int c) {
        const uint32_t base = sb + st * STAGE_SM;
#pragma unroll
        for (int i = 0; i < 2; i++) {
            const int row = rowL;            // both ops same row (segs consecutive)
            const int seg = segL + i;
            const size_t gA = (size_t)(by * 128 + row) * K_SZ + c * 32 + seg * 8;
            const size_t gB = (size_t)(bx * 128 + row) * K_SZ + c * 32 + seg * 8;
            const uint32_t so = base + (uint32_t)row * LDSM_STRIDE + seg * 16;
            cp16(so,               g_ahi + gA);
            cp16(so +     TILE_SM, g_alo + gA);
            cp16(so + 2 * TILE_SM, g_bhi + gB);
            cp16(so + 3 * TILE_SM, g_blo + gB);
        }
    };

    // ---- compute one chunk from stage st ----
    auto compute = [&](int st) {
        const uint32_t base = sb + st * STAGE_SM;
#pragma unroll
        for (int s = 0; s < 2; s++) {
            const uint32_t ks = s * 32;                 // 16 bf16 = 32B per k16 step
            const uint32_t aB = base + a_off + ks;                 // Ah tile
            const uint32_t bB = base + 2 * TILE_SM + b_off + ks;   // Bh tile
            uint32_t a[16], bh[8], bl[8];
#pragma unroll
            for (int mi = 0; mi < 4; mi++)
                LDSM4(a[mi*4+0], a[mi*4+1], a[mi*4+2], a[mi*4+3], aB + mi * 16 * LDSM_STRIDE);
#pragma unroll
            for (int nj = 0; nj < 2; nj++)
                LDSM4(bh[nj*4+0], bh[nj*4+1], bh[nj*4+2], bh[nj*4+3], bB + nj * 16 * LDSM_STRIDE);
            // pass 1: Ah * Bh
#pragma unroll
            for (int mi = 0; mi < 4; mi++)
#pragma unroll
                for (int ni = 0; ni < 4; ni++)
                    MMA16816(acc[mi][ni], &a[mi*4], bh[(ni>>1)*4 + (ni&1)*2], bh[(ni>>1)*4 + (ni&1)*2 + 1]);
            // pass 2: Ah * Bl
#pragma unroll
            for (int nj = 0; nj < 2; nj++)
                LDSM4(bl[nj*4+0], bl[nj*4+1], bl[nj*4+2], bl[nj*4+3], bB + TILE_SM + nj * 16 * LDSM_STRIDE);
#pragma unroll
            for (int mi = 0; mi < 4; mi++)
#pragma unroll
                for (int ni = 0; ni < 4; ni++)
                    MMA16816(acc[mi][ni], &a[mi*4], bl[(ni>>1)*4 + (ni&1)*2], bl[(ni>>1)*4 + (ni&1)*2 + 1]);
            // pass 3: Al * Bh
#pragma unroll
            for (int mi = 0; mi < 4; mi++)
                LDSM4(a[mi*4+0], a[mi*4+1], a[mi*4+2], a[mi*4+3], aB + TILE_SM + mi * 16 * LDSM_STRIDE);
#pragma unroll
            for (int mi = 0; mi < 4; mi++)
#pragma unroll
                for (int ni = 0; ni < 4; ni++)
                    MMA16816(acc[mi][ni], &a[mi*4], bh[(ni>>1)*4 + (ni&1)*2], bh[(ni>>1)*4 + (ni&1)*2 + 1]);
        }
    };

    // ---- pipelined main loop ----
    load_stage(0, 0); CP_COMMIT();
    for (int c = 0; c < KCHUNKS; c++) {
        if (c + 1 < KCHUNKS) {
            load_stage((c + 1) & 1, c + 1); CP_COMMIT();
            CP_WAIT1();
        } else {
            CP_WAIT0();
        }
        __syncthreads();
        compute(c & 1);
        __syncthreads();
    }

    // ---- epilogue: bias + activation -> g_gate / g_val ----
    const int n0 = bx * 128;
    const bool is_gate = (bx < 16);
    float* dst = is_gate ? g_gate : g_val;
    const int cadj = is_gate ? 0 : C_SZ;
    const int r_in  = lane >> 2;
    const int cpair = (lane & 3) * 2;

#pragma unroll
    for (int mi = 0; mi < 4; mi++) {
        const int gm = by * 128 + m_off + mi * 16 + r_in;
        float* row0 = dst + (size_t)gm * C_SZ + (n0 - cadj);
        float* row1 = row0 + (size_t)8 * C_SZ;
#pragma unroll
        for (int ni = 0; ni < 4; ni++) {
            const int col = n_off + ni * 8 + cpair;
            const float b0 = __ldg(bias + n0 + col);
            const float b1 = __ldg(bias + n0 + col + 1);
            float v0 = acc[mi][ni][0] + b0, v1 = acc[mi][ni][1] + b1;
            float v2 = acc[mi][ni][2] + b0, v3 = acc[mi][ni][3] + b1;
            float o0, o1, o2, o3;
            if (is_gate) { o0 = act_sig(v0);  o1 = act_sig(v1);  o2 = act_sig(v2);  o3 = act_sig(v3); }
            else         { o0 = act_tanh(v0); o1 = act_tanh(v1); o2 = act_tanh(v2); o3 = act_tanh(v3); }
            *(float2*)(row0 + col) = make_float2(o0, o1);
            *(float2*)(row1 + col) = make_float2(o2, o3);
        }
    }
}

// ---------------- scan (unchanged) ----------------
#define SCAN_U 16
__global__ __launch_bounds__(128) void scan_kernel(float* __restrict__ out)
{
    const int s = blockIdx.x * blockDim.x + threadIdx.x;
    if (s >= B_SZ * C_SZ) return;
    const int bb = s / C_SZ;
    const int c  = s - bb * C_SZ;
    const size_t base = (size_t)bb * T_SZ * C_SZ + c;

    const float* gp = g_gate + base;
    const float* vp = g_val  + base;
    float*       op = out    + base;

    float h = 0.0f;
    for (int t = 0; t < T_SZ; t += SCAN_U) {
        float g[SCAN_U], v[SCAN_U];
#pragma unroll
        for (int u = 0; u < SCAN_U; u++) {
            g[u] = __ldg(gp + (size_t)(t + u) * C_SZ);
            v[u] = __ldg(vp + (size_t)(t + u) * C_SZ);
        }
#pragma unroll
        for (int u = 0; u < SCAN_U; u++) {
            h = fmaf(g[u], h, v[u]);
            op[(size_t)(t + u) * C_SZ] = h;
        }
    }
}

// ---------------- launch ----------------
extern "C" void kernel_launch(void* const* d_in, const int* in_sizes, int n_in,
                              void* d_out, int out_size)
{
    const float* x  = (const float*)d_in[0];  // [B,T,C]
    const float* W  = (const float*)d_in[1];  // [2C,C]
    const float* bi = (const float*)d_in[2];  // [2C]
    float* out = (float*)d_out;               // [B,T,C]

    cudaFuncSetAttribute(gemm_mma, cudaFuncAttributeMaxDynamicSharedMemorySize, GEMM_SMEM);

    const size_t total4 = ((size_t)M_SZ * K_SZ + (size_t)N_SZ * K_SZ) / 4;
    convert_kernel<<<(unsigned)((total4 + 255) / 256), 256>>>(x, W);

    gemm_mma<<<dim3(32, 128), 256, GEMM_SMEM>>>(bi);

    scan_kernel<<<(B_SZ * C_SZ + 127) / 128, 128>>>(out);
}

// round 6
// speedup vs baseline: 2.9860x; 1.6910x over previous
#include <cuda_runtime.h>
#include <cuda_fp16.h>
#include <cstdint>
#include <math.h>

// ---------------- problem shapes ----------------
#define B_SZ 4
#define T_SZ 4096
#define C_SZ 2048
#define M_SZ (B_SZ * T_SZ)   // 16384
#define N_SZ (2 * C_SZ)      // 4096
#define K_SZ C_SZ            // 2048

// ---------------- device scratch ----------------
__device__ float g_gate[(size_t)M_SZ * C_SZ];
__device__ float g_val [(size_t)M_SZ * C_SZ];
__device__ __half g_a16[(size_t)M_SZ * K_SZ];          // x rounded to fp16
__device__ __half g_bhi[(size_t)N_SZ * K_SZ];          // W hi
__device__ __half g_blo[(size_t)N_SZ * K_SZ];          // W lo (residual)

// scan chunk summaries: 32 chunks x 8192 sequences
#define SCAN_CH 128
#define SCAN_NCH (T_SZ / SCAN_CH)   // 32
#define NSEQ (B_SZ * C_SZ)          // 8192
__device__ float g_Gc [SCAN_NCH * NSEQ];
__device__ float g_Vc [SCAN_NCH * NSEQ];
__device__ float g_Hin[SCAN_NCH * NSEQ];

// ---------------- helpers ----------------
__device__ __forceinline__ uint32_t smem_u32(const void* p) {
    uint32_t a;
    asm("{ .reg .u64 t; cvta.to.shared.u64 t, %1; cvt.u32.u64 %0, t; }" : "=r"(a) : "l"(p));
    return a;
}
__device__ __forceinline__ void cp16(uint32_t dst, const void* src) {
    asm volatile("cp.async.cg.shared.global [%0], [%1], 16;" :: "r"(dst), "l"(src));
}
#define CP_COMMIT() asm volatile("cp.async.commit_group;" ::: "memory")
#define CP_WAIT0()  asm volatile("cp.async.wait_group 0;" ::: "memory")
#define CP_WAIT1()  asm volatile("cp.async.wait_group 1;" ::: "memory")

#define LDSM4(r0, r1, r2, r3, addr) \
    asm volatile("ldmatrix.sync.aligned.m8n8.x4.shared.b16 {%0,%1,%2,%3}, [%4];" \
        : "=r"(r0), "=r"(r1), "=r"(r2), "=r"(r3) : "r"(addr))

// fp16 inputs, fp32 accumulate
#define MMA16816(d, a, b0, b1) \
    asm volatile("mma.sync.aligned.m16n8k16.row.col.f32.f16.f16.f32 " \
        "{%0,%1,%2,%3},{%4,%5,%6,%7},{%8,%9},{%0,%1,%2,%3};" \
        : "+f"((d)[0]), "+f"((d)[1]), "+f"((d)[2]), "+f"((d)[3]) \
        : "r"((a)[0]), "r"((a)[1]), "r"((a)[2]), "r"((a)[3]), "r"(b0), "r"(b1))

__device__ __forceinline__ float act_sig(float v)  { return 1.0f / (1.0f + __expf(-v)); }
__device__ __forceinline__ float act_tanh(float v) { return 1.0f - 2.0f / (__expf(2.0f * v) + 1.0f); }

// ---------------- convert: x -> fp16, W -> fp16 hi/lo split ----------------
__global__ __launch_bounds__(256) void convert_kernel(
    const float* __restrict__ x, const float* __restrict__ W)
{
    const size_t MK4 = (size_t)M_SZ * K_SZ / 4;
    const size_t NK4 = (size_t)N_SZ * K_SZ / 4;
    size_t i = (size_t)blockIdx.x * blockDim.x + threadIdx.x;
    if (i >= MK4 + NK4) return;

    if (i < MK4) {
        float4 v = ((const float4*)x)[i];
        __half2 h01 = __floats2half2_rn(v.x, v.y);
        __half2 h23 = __floats2half2_rn(v.z, v.w);
        uint2 o;
        o.x = *(uint32_t*)&h01; o.y = *(uint32_t*)&h23;
        ((uint2*)g_a16)[i] = o;
    } else {
        size_t j = i - MK4;
        float4 v = ((const float4*)W)[j];
        float vv[4] = {v.x, v.y, v.z, v.w};
        __half hs[4], ls[4];
#pragma unroll
        for (int u = 0; u < 4; u++) {
            __half hb = __float2half_rn(vv[u]);
            float r = vv[u] - __half2float(hb);
            hs[u] = hb;
            ls[u] = __float2half_rn(r);
        }
        uint2 oh, ol;
        __half2 t0 = __halves2half2(hs[0], hs[1]), t1 = __halves2half2(hs[2], hs[3]);
        __half2 t2 = __halves2half2(ls[0], ls[1]), t3 = __halves2half2(ls[2], ls[3]);
        oh.x = *(uint32_t*)&t0; oh.y = *(uint32_t*)&t1;
        ol.x = *(uint32_t*)&t2; ol.y = *(uint32_t*)&t3;
        ((uint2*)g_bhi)[j] = oh;
        ((uint2*)g_blo)[j] = ol;
    }
}

// ---------------- HMMA GEMM: C = A * W^T (+bias), fused activation ----------------
// CTA tile 128x128, BK=32. 8 warps: 2(M) x 4(N), warp tile 64x32.
// smem per stage: 3 tiles (A16, Bhi, Blo), each 128 rows x 32 fp16, row stride 80B.
#define LDSM_STRIDE 80
#define TILE_SM 10240            // 128 * 80
#define STAGE_SM (3 * TILE_SM)   // 30720
#define GEMM_SMEM (2 * STAGE_SM) // 61440
#define KCHUNKS 64               // 2048 / 32

__global__ __launch_bounds__(256, 2) void gemm_mma(const float* __restrict__ bias)
{
    extern __shared__ char smem[];
    const uint32_t sb = smem_u32(smem);
    const int tid  = threadIdx.x;
    const int lane = tid & 31;
    const int wid  = tid >> 5;
    const int bx = blockIdx.x;   // N tile 0..31
    const int by = blockIdx.y;   // M tile 0..127

    const int m_off = (wid & 1) * 64;
    const int n_off = (wid >> 1) * 32;

    float acc[4][4][4];
#pragma unroll
    for (int mi = 0; mi < 4; mi++)
#pragma unroll
        for (int ni = 0; ni < 4; ni++)
#pragma unroll
            for (int u = 0; u < 4; u++) acc[mi][ni][u] = 0.0f;

    // ldmatrix per-lane address components
    const uint32_t a_off = (uint32_t)(m_off + (lane & 15)) * LDSM_STRIDE + ((lane >> 4) * 16);
    const uint32_t b_off = (uint32_t)(n_off + (lane & 7) + (((lane >> 3) >> 1) * 8)) * LDSM_STRIDE
                           + (((lane >> 3) & 1) * 16);

    // cp.async mapping: per tile, thread does ops o = 2*tid, 2*tid+1; row = o>>2, seg = o&3
    const int o0   = 2 * tid;
    const int rowL = o0 >> 2;            // 0..127
    const int segL = o0 & 3;             // 0 or 2 (i adds 0/1)

    auto load_stage = [&](int st, int c) {
        const uint32_t base = sb + st * STAGE_SM;
#pragma unroll
        for (int i = 0; i < 2; i++) {
            const int row = rowL;
            const int seg = segL + i;
            const size_t gA = (size_t)(by * 128 + row) * K_SZ + c * 32 + seg * 8;
            const size_t gB = (size_t)(bx * 128 + row) * K_SZ + c * 32 + seg * 8;
            const uint32_t so = base + (uint32_t)row * LDSM_STRIDE + seg * 16;
            cp16(so,               g_a16 + gA);
            cp16(so +     TILE_SM, g_bhi + gB);
            cp16(so + 2 * TILE_SM, g_blo + gB);
        }
    };

    auto compute = [&](int st) {
        const uint32_t base = sb + st * STAGE_SM;
#pragma unroll
        for (int s = 0; s < 2; s++) {
            const uint32_t ks = s * 32;                        // 16 fp16 = 32B per k16 step
            const uint32_t aB  = base + a_off + ks;            // A tile
            const uint32_t bhB = base + TILE_SM + b_off + ks;  // Bhi tile
            const uint32_t blB = base + 2 * TILE_SM + b_off + ks;
            uint32_t a[16], bh[8], bl[8];
#pragma unroll
            for (int mi = 0; mi < 4; mi++)
                LDSM4(a[mi*4+0], a[mi*4+1], a[mi*4+2], a[mi*4+3], aB + mi * 16 * LDSM_STRIDE);
#pragma unroll
            for (int nj = 0; nj < 2; nj++)
                LDSM4(bh[nj*4+0], bh[nj*4+1], bh[nj*4+2], bh[nj*4+3], bhB + nj * 16 * LDSM_STRIDE);
            // pass 1: A * Whi
#pragma unroll
            for (int mi = 0; mi < 4; mi++)
#pragma unroll
                for (int ni = 0; ni < 4; ni++)
                    MMA16816(acc[mi][ni], &a[mi*4], bh[(ni>>1)*4 + (ni&1)*2], bh[(ni>>1)*4 + (ni&1)*2 + 1]);
            // pass 2: A * Wlo
#pragma unroll
            for (int nj = 0; nj < 2; nj++)
                LDSM4(bl[nj*4+0], bl[nj*4+1], bl[nj*4+2], bl[nj*4+3], blB + nj * 16 * LDSM_STRIDE);
#pragma unroll
            for (int mi = 0; mi < 4; mi++)
#pragma unroll
                for (int ni = 0; ni < 4; ni++)
                    MMA16816(acc[mi][ni], &a[mi*4], bl[(ni>>1)*4 + (ni&1)*2], bl[(ni>>1)*4 + (ni&1)*2 + 1]);
        }
    };

    // ---- pipelined main loop ----
    load_stage(0, 0); CP_COMMIT();
    for (int c = 0; c < KCHUNKS; c++) {
        if (c + 1 < KCHUNKS) {
            load_stage((c + 1) & 1, c + 1); CP_COMMIT();
            CP_WAIT1();
        } else {
            CP_WAIT0();
        }
        __syncthreads();
        compute(c & 1);
        __syncthreads();
    }

    // ---- epilogue: bias + activation -> g_gate / g_val ----
    const int n0 = bx * 128;
    const bool is_gate = (bx < 16);
    float* dst = is_gate ? g_gate : g_val;
    const int cadj = is_gate ? 0 : C_SZ;
    const int r_in  = lane >> 2;
    const int cpair = (lane & 3) * 2;

#pragma unroll
    for (int mi = 0; mi < 4; mi++) {
        const int gm = by * 128 + m_off + mi * 16 + r_in;
        float* row0 = dst + (size_t)gm * C_SZ + (n0 - cadj);
        float* row1 = row0 + (size_t)8 * C_SZ;
#pragma unroll
        for (int ni = 0; ni < 4; ni++) {
            const int col = n_off + ni * 8 + cpair;
            const float b0 = __ldg(bias + n0 + col);
            const float b1 = __ldg(bias + n0 + col + 1);
            float v0 = acc[mi][ni][0] + b0, v1 = acc[mi][ni][1] + b1;
            float v2 = acc[mi][ni][2] + b0, v3 = acc[mi][ni][3] + b1;
            float o0, o1, o2, o3;
            if (is_gate) { o0 = act_sig(v0);  o1 = act_sig(v1);  o2 = act_sig(v2);  o3 = act_sig(v3); }
            else         { o0 = act_tanh(v0); o1 = act_tanh(v1); o2 = act_tanh(v2); o3 = act_tanh(v3); }
            *(float2*)(row0 + col) = make_float2(o0, o1);
            *(float2*)(row1 + col) = make_float2(o2, o3);
        }
    }
}

// ---------------- chunked scan: 3 passes ----------------
// pass1: per (b,c,chunk) compute G = prod(g), V = local scan end (h_in = 0)
__global__ __launch_bounds__(256) void scan_pass1()
{
    const int id = blockIdx.x * blockDim.x + threadIdx.x;
    if (id >= NSEQ * SCAN_NCH) return;
    const int chunk = id / NSEQ;
    const int s     = id - chunk * NSEQ;     // b*C + c
    const int bb = s >> 11;                  // /2048
    const int c  = s & 2047;
    const size_t base = (size_t)bb * T_SZ * C_SZ + (size_t)chunk * SCAN_CH * C_SZ + c;

    const float* gp = g_gate + base;
    const float* vp = g_val  + base;

    float G = 1.0f, V = 0.0f;
#pragma unroll 1
    for (int t = 0; t < SCAN_CH; t += 8) {
        float g[8], v[8];
#pragma unroll
        for (int u = 0; u < 8; u++) {
            g[u] = __ldg(gp + (size_t)(t + u) * C_SZ);
            v[u] = __ldg(vp + (size_t)(t + u) * C_SZ);
        }
#pragma unroll
        for (int u = 0; u < 8; u++) {
            V = fmaf(g[u], V, v[u]);
            G *= g[u];
        }
    }
    g_Gc[chunk * NSEQ + s] = G;
    g_Vc[chunk * NSEQ + s] = V;
}

// pass2: scan the chunk summaries; write carry-in per chunk
__global__ __launch_bounds__(256) void scan_pass2()
{
    const int s = blockIdx.x * blockDim.x + threadIdx.x;
    if (s >= NSEQ) return;
    float h = 0.0f;
#pragma unroll
    for (int j = 0; j < SCAN_NCH; j++) {
        g_Hin[j * NSEQ + s] = h;
        h = fmaf(g_Gc[j * NSEQ + s], h, g_Vc[j * NSEQ + s]);
    }
}

// pass3: apply carry, write final h
__global__ __launch_bounds__(256) void scan_pass3(float* __restrict__ out)
{
    const int id = blockIdx.x * blockDim.x + threadIdx.x;
    if (id >= NSEQ * SCAN_NCH) return;
    const int chunk = id / NSEQ;
    const int s     = id - chunk * NSEQ;
    const int bb = s >> 11;
    const int c  = s & 2047;
    const size_t base = (size_t)bb * T_SZ * C_SZ + (size_t)chunk * SCAN_CH * C_SZ + c;

    const float* gp = g_gate + base;
    const float* vp = g_val  + base;
    float*       op = out    + base;

    float h = g_Hin[chunk * NSEQ + s];
#pragma unroll 1
    for (int t = 0; t < SCAN_CH; t += 8) {
        float g[8], v[8];
#pragma unroll
        for (int u = 0; u < 8; u++) {
            g[u] = __ldg(gp + (size_t)(t + u) * C_SZ);
            v[u] = __ldg(vp + (size_t)(t + u) * C_SZ);
        }
#pragma unroll
        for (int u = 0; u < 8; u++) {
            h = fmaf(g[u], h, v[u]);
            op[(size_t)(t + u) * C_SZ] = h;
        }
    }
}

// ---------------- launch ----------------
extern "C" void kernel_launch(void* const* d_in, const int* in_sizes, int n_in,
                              void* d_out, int out_size)
{
    const float* x  = (const float*)d_in[0];  // [B,T,C]
    const float* W  = (const float*)d_in[1];  // [2C,C]
    const float* bi = (const float*)d_in[2];  // [2C]
    float* out = (float*)d_out;               // [B,T,C]

    cudaFuncSetAttribute(gemm_mma, cudaFuncAttributeMaxDynamicSharedMemorySize, GEMM_SMEM);

    const size_t total4 = ((size_t)M_SZ * K_SZ + (size_t)N_SZ * K_SZ) / 4;
    convert_kernel<<<(unsigned)((total4 + 255) / 256), 256>>>(x, W);

    gemm_mma<<<dim3(32, 128), 256, GEMM_SMEM>>>(bi);

    const int nwork = NSEQ * SCAN_NCH;       // 262144
    scan_pass1<<<(nwork + 255) / 256, 256>>>();
    scan_pass2<<<(NSEQ + 255) / 256, 256>>>();
    scan_pass3<<<(nwork + 255) / 256, 256>>>(out);
}

// round 7
// speedup vs baseline: 2.9992x; 1.0044x over previous
#include <cuda_runtime.h>
#include <cuda_fp16.h>
#include <cstdint>
#include <math.h>

// ---------------- problem shapes ----------------
#define B_SZ 4
#define T_SZ 4096
#define C_SZ 2048
#define M_SZ (B_SZ * T_SZ)   // 16384
#define N_SZ (2 * C_SZ)      // 4096
#define K_SZ C_SZ            // 2048

// ---------------- device scratch ----------------
__device__ float g_gate[(size_t)M_SZ * C_SZ];
__device__ float g_val [(size_t)M_SZ * C_SZ];
__device__ __half g_a16[(size_t)M_SZ * K_SZ];          // x rounded to fp16
__device__ __half g_bhi[(size_t)N_SZ * K_SZ];          // W hi
__device__ __half g_blo[(size_t)N_SZ * K_SZ];          // W lo (residual)

// scan chunk summaries: 32 chunks x 8192 sequences
#define SCAN_CH 128
#define SCAN_NCH (T_SZ / SCAN_CH)   // 32
#define NSEQ (B_SZ * C_SZ)          // 8192
__device__ float g_Gc [SCAN_NCH * NSEQ];
__device__ float g_Vc [SCAN_NCH * NSEQ];
__device__ float g_Hin[SCAN_NCH * NSEQ];

// ---------------- helpers ----------------
__device__ __forceinline__ uint32_t smem_u32(const void* p) {
    uint32_t a;
    asm("{ .reg .u64 t; cvta.to.shared.u64 t, %1; cvt.u32.u64 %0, t; }" : "=r"(a) : "l"(p));
    return a;
}
__device__ __forceinline__ void cp16(uint32_t dst, const void* src) {
    asm volatile("cp.async.cg.shared.global [%0], [%1], 16;" :: "r"(dst), "l"(src));
}
#define CP_COMMIT() asm volatile("cp.async.commit_group;" ::: "memory")
#define CP_WAIT0()  asm volatile("cp.async.wait_group 0;" ::: "memory")
#define CP_WAIT1()  asm volatile("cp.async.wait_group 1;" ::: "memory")

#define LDSM4(r0, r1, r2, r3, addr) \
    asm volatile("ldmatrix.sync.aligned.m8n8.x4.shared.b16 {%0,%1,%2,%3}, [%4];" \
        : "=r"(r0), "=r"(r1), "=r"(r2), "=r"(r3) : "r"(addr))

// fp16 inputs, fp32 accumulate
#define MMA16816(d, a, b0, b1) \
    asm volatile("mma.sync.aligned.m16n8k16.row.col.f32.f16.f16.f32 " \
        "{%0,%1,%2,%3},{%4,%5,%6,%7},{%8,%9},{%0,%1,%2,%3};" \
        : "+f"((d)[0]), "+f"((d)[1]), "+f"((d)[2]), "+f"((d)[3]) \
        : "r"((a)[0]), "r"((a)[1]), "r"((a)[2]), "r"((a)[3]), "r"(b0), "r"(b1))

__device__ __forceinline__ float act_sig(float v)  { return 1.0f / (1.0f + __expf(-v)); }
__device__ __forceinline__ float act_tanh(float v) { return 1.0f - 2.0f / (__expf(2.0f * v) + 1.0f); }

// ---------------- convert: x -> fp16, W -> fp16 hi/lo split ----------------
__global__ __launch_bounds__(256) void convert_kernel(
    const float* __restrict__ x, const float* __restrict__ W)
{
    const size_t MK4 = (size_t)M_SZ * K_SZ / 4;
    const size_t NK4 = (size_t)N_SZ * K_SZ / 4;
    size_t i = (size_t)blockIdx.x * blockDim.x + threadIdx.x;
    if (i >= MK4 + NK4) return;

    if (i < MK4) {
        float4 v = ((const float4*)x)[i];
        __half2 h01 = __floats2half2_rn(v.x, v.y);
        __half2 h23 = __floats2half2_rn(v.z, v.w);
        uint2 o;
        o.x = *(uint32_t*)&h01; o.y = *(uint32_t*)&h23;
        ((uint2*)g_a16)[i] = o;
    } else {
        size_t j = i - MK4;
        float4 v = ((const float4*)W)[j];
        float vv[4] = {v.x, v.y, v.z, v.w};
        __half hs[4], ls[4];
#pragma unroll
        for (int u = 0; u < 4; u++) {
            __half hb = __float2half_rn(vv[u]);
            float r = vv[u] - __half2float(hb);
            hs[u] = hb;
            ls[u] = __float2half_rn(r);
        }
        uint2 oh, ol;
        __half2 t0 = __halves2half2(hs[0], hs[1]), t1 = __halves2half2(hs[2], hs[3]);
        __half2 t2 = __halves2half2(ls[0], ls[1]), t3 = __halves2half2(ls[2], ls[3]);
        oh.x = *(uint32_t*)&t0; oh.y = *(uint32_t*)&t1;
        ol.x = *(uint32_t*)&t2; ol.y = *(uint32_t*)&t3;
        ((uint2*)g_bhi)[j] = oh;
        ((uint2*)g_blo)[j] = ol;
    }
}

// ---------------- HMMA GEMM: C = A * W^T (+bias), fused activation ----------------
// CTA tile 128x128, BK=32. 8 warps: 2(M) x 4(N), warp tile 64x32.
// smem per stage: 3 tiles (A16, Bhi, Blo), each 128 rows x 32 fp16, row stride 80B.
#define LDSM_STRIDE 80
#define TILE_SM 10240            // 128 * 80
#define STAGE_SM (3 * TILE_SM)   // 30720
#define GEMM_SMEM (2 * STAGE_SM) // 61440
#define KCHUNKS 64               // 2048 / 32

__global__ __launch_bounds__(256, 2) void gemm_mma(const float* __restrict__ bias)
{
    extern __shared__ char smem[];
    const uint32_t sb = smem_u32(smem);
    const int tid  = threadIdx.x;
    const int lane = tid & 31;
    const int wid  = tid >> 5;
    const int bx = blockIdx.x;   // N tile 0..31
    const int by = blockIdx.y;   // M tile 0..127

    const int m_off = (wid & 1) * 64;
    const int n_off = (wid >> 1) * 32;

    float acc[4][4][4];
#pragma unroll
    for (int mi = 0; mi < 4; mi++)
#pragma unroll
        for (int ni = 0; ni < 4; ni++)
#pragma unroll
            for (int u = 0; u < 4; u++) acc[mi][ni][u] = 0.0f;

    // ldmatrix per-lane address components
    const uint32_t a_off = (uint32_t)(m_off + (lane & 15)) * LDSM_STRIDE + ((lane >> 4) * 16);
    const uint32_t b_off = (uint32_t)(n_off + (lane & 7) + (((lane >> 3) >> 1) * 8)) * LDSM_STRIDE
                           + (((lane >> 3) & 1) * 16);

    // cp.async mapping: per tile, thread does ops o = 2*tid, 2*tid+1; row = o>>2, seg = o&3
    const int o0   = 2 * tid;
    const int rowL = o0 >> 2;            // 0..127
    const int segL = o0 & 3;             // 0 or 2 (i adds 0/1)

    auto load_stage = [&](int st, int c) {
        const uint32_t base = sb + st * STAGE_SM;
#pragma unroll
        for (int i = 0; i < 2; i++) {
            const int row = rowL;
            const int seg = segL + i;
            const size_t gA = (size_t)(by * 128 + row) * K_SZ + c * 32 + seg * 8;
            const size_t gB = (size_t)(bx * 128 + row) * K_SZ + c * 32 + seg * 8;
            const uint32_t so = base + (uint32_t)row * LDSM_STRIDE + seg * 16;
            cp16(so,               g_a16 + gA);
            cp16(so +     TILE_SM, g_bhi + gB);
            cp16(so + 2 * TILE_SM, g_blo + gB);
        }
    };

    auto compute = [&](int st) {
        const uint32_t base = sb + st * STAGE_SM;
#pragma unroll
        for (int s = 0; s < 2; s++) {
            const uint32_t ks = s * 32;                        // 16 fp16 = 32B per k16 step
            const uint32_t aB  = base + a_off + ks;            // A tile
            const uint32_t bhB = base + TILE_SM + b_off + ks;  // Bhi tile
            const uint32_t blB = base + 2 * TILE_SM + b_off + ks;
            uint32_t a[16], bh[8], bl[8];
#pragma unroll
            for (int mi = 0; mi < 4; mi++)
                LDSM4(a[mi*4+0], a[mi*4+1], a[mi*4+2], a[mi*4+3], aB + mi * 16 * LDSM_STRIDE);
#pragma unroll
            for (int nj = 0; nj < 2; nj++)
                LDSM4(bh[nj*4+0], bh[nj*4+1], bh[nj*4+2], bh[nj*4+3], bhB + nj * 16 * LDSM_STRIDE);
            // pass 1: A * Whi
#pragma unroll
            for (int mi = 0; mi < 4; mi++)
#pragma unroll
                for (int ni = 0; ni < 4; ni++)
                    MMA16816(acc[mi][ni], &a[mi*4], bh[(ni>>1)*4 + (ni&1)*2], bh[(ni>>1)*4 + (ni&1)*2 + 1]);
            // pass 2: A * Wlo
#pragma unroll
            for (int nj = 0; nj < 2; nj++)
                LDSM4(bl[nj*4+0], bl[nj*4+1], bl[nj*4+2], bl[nj*4+3], blB + nj * 16 * LDSM_STRIDE);
#pragma unroll
            for (int mi = 0; mi < 4; mi++)
#pragma unroll
                for (int ni = 0; ni < 4; ni++)
                    MMA16816(acc[mi][ni], &a[mi*4], bl[(ni>>1)*4 + (ni&1)*2], bl[(ni>>1)*4 + (ni&1)*2 + 1]);
        }
    };

    // ---- pipelined main loop ----
    load_stage(0, 0); CP_COMMIT();
    for (int c = 0; c < KCHUNKS; c++) {
        if (c + 1 < KCHUNKS) {
            load_stage((c + 1) & 1, c + 1); CP_COMMIT();
            CP_WAIT1();
        } else {
            CP_WAIT0();
        }
        __syncthreads();
        compute(c & 1);
        __syncthreads();
    }

    // ---- epilogue: bias + activation -> g_gate / g_val ----
    const int n0 = bx * 128;
    const bool is_gate = (bx < 16);
    float* dst = is_gate ? g_gate : g_val;
    const int cadj = is_gate ? 0 : C_SZ;
    const int r_in  = lane >> 2;
    const int cpair = (lane & 3) * 2;

#pragma unroll
    for (int mi = 0; mi < 4; mi++) {
        const int gm = by * 128 + m_off + mi * 16 + r_in;
        float* row0 = dst + (size_t)gm * C_SZ + (n0 - cadj);
        float* row1 = row0 + (size_t)8 * C_SZ;
#pragma unroll
        for (int ni = 0; ni < 4; ni++) {
            const int col = n_off + ni * 8 + cpair;
            const float b0 = __ldg(bias + n0 + col);
            const float b1 = __ldg(bias + n0 + col + 1);
            float v0 = acc[mi][ni][0] + b0, v1 = acc[mi][ni][1] + b1;
            float v2 = acc[mi][ni][2] + b0, v3 = acc[mi][ni][3] + b1;
            float o0, o1, o2, o3;
            if (is_gate) { o0 = act_sig(v0);  o1 = act_sig(v1);  o2 = act_sig(v2);  o3 = act_sig(v3); }
            else         { o0 = act_tanh(v0); o1 = act_tanh(v1); o2 = act_tanh(v2); o3 = act_tanh(v3); }
            *(float2*)(row0 + col) = make_float2(o0, o1);
            *(float2*)(row1 + col) = make_float2(o2, o3);
        }
    }
}

// ---------------- chunked scan: 3 passes ----------------
// pass1: per (b,c,chunk) compute G = prod(g), V = local scan end (h_in = 0)
__global__ __launch_bounds__(256) void scan_pass1()
{
    const int id = blockIdx.x * blockDim.x + threadIdx.x;
    if (id >= NSEQ * SCAN_NCH) return;
    const int chunk = id / NSEQ;
    const int s     = id - chunk * NSEQ;     // b*C + c
    const int bb = s >> 11;                  // /2048
    const int c  = s & 2047;
    const size_t base = (size_t)bb * T_SZ * C_SZ + (size_t)chunk * SCAN_CH * C_SZ + c;

    const float* gp = g_gate + base;
    const float* vp = g_val  + base;

    float G = 1.0f, V = 0.0f;
#pragma unroll 1
    for (int t = 0; t < SCAN_CH; t += 8) {
        float g[8], v[8];
#pragma unroll
        for (int u = 0; u < 8; u++) {
            g[u] = __ldg(gp + (size_t)(t + u) * C_SZ);
            v[u] = __ldg(vp + (size_t)(t + u) * C_SZ);
        }
#pragma unroll
        for (int u = 0; u < 8; u++) {
            V = fmaf(g[u], V, v[u]);
            G *= g[u];
        }
    }
    g_Gc[chunk * NSEQ + s] = G;
    g_Vc[chunk * NSEQ + s] = V;
}

// pass2: scan the chunk summaries; write carry-in per chunk
__global__ __launch_bounds__(256) void scan_pass2()
{
    const int s = blockIdx.x * blockDim.x + threadIdx.x;
    if (s >= NSEQ) return;
    float h = 0.0f;
#pragma unroll
    for (int j = 0; j < SCAN_NCH; j++) {
        g_Hin[j * NSEQ + s] = h;
        h = fmaf(g_Gc[j * NSEQ + s], h, g_Vc[j * NSEQ + s]);
    }
}

// pass3: apply carry, write final h
__global__ __launch_bounds__(256) void scan_pass3(float* __restrict__ out)
{
    const int id = blockIdx.x * blockDim.x + threadIdx.x;
    if (id >= NSEQ * SCAN_NCH) return;
    const int chunk = id / NSEQ;
    const int s     = id - chunk * NSEQ;
    const int bb = s >> 11;
    const int c  = s & 2047;
    const size_t base = (size_t)bb * T_SZ * C_SZ + (size_t)chunk * SCAN_CH * C_SZ + c;

    const float* gp = g_gate + base;
    const float* vp = g_val  + base;
    float*       op = out    + base;

    float h = g_Hin[chunk * NSEQ + s];
#pragma unroll 1
    for (int t = 0; t < SCAN_CH; t += 8) {
        float g[8], v[8];
#pragma unroll
        for (int u = 0; u < 8; u++) {
            g[u] = __ldg(gp + (size_t)(t + u) * C_SZ);
            v[u] = __ldg(vp + (size_t)(t + u) * C_SZ);
        }
#pragma unroll
        for (int u = 0; u < 8; u++) {
            h = fmaf(g[u], h, v[u]);
            op[(size_t)(t + u) * C_SZ] = h;
        }
    }
}

// ---------------- launch ----------------
extern "C" void kernel_launch(void* const* d_in, const int* in_sizes, int n_in,
                              void* d_out, int out_size)
{
    const float* x  = (const float*)d_in[0];  // [B,T,C]
    const float* W  = (const float*)d_in[1];  // [2C,C]
    const float* bi = (const float*)d_in[2];  // [2C]
    float* out = (float*)d_out;               // [B,T,C]

    cudaFuncSetAttribute(gemm_mma, cudaFuncAttributeMaxDynamicSharedMemorySize, GEMM_SMEM);

    const size_t total4 = ((size_t)M_SZ * K_SZ + (size_t)N_SZ * K_SZ) / 4;
    convert_kernel<<<(unsigned)((total4 + 255) / 256), 256>>>(x, W);

    gemm_mma<<<dim3(32, 128), 256, GEMM_SMEM>>>(bi);

    const int nwork = NSEQ * SCAN_NCH;       // 262144
    scan_pass1<<<(nwork + 255) / 256, 256>>>();
    scan_pass2<<<(NSEQ + 255) / 256, 256>>>();
    scan_pass3<<<(nwork + 255) / 256, 256>>>(out);
}

// round 8
// speedup vs baseline: 4.2017x; 1.4010x over previous
#include <cuda_runtime.h>
#include <cuda_fp16.h>
#include <cstdint>
#include <math.h>

// ---------------- problem shapes ----------------
#define B_SZ 4
#define T_SZ 4096
#define C_SZ 2048
#define M_SZ (B_SZ * T_SZ)   // 16384
#define N_SZ (2 * C_SZ)      // 4096
#define K_SZ C_SZ            // 2048

// ---------------- device scratch ----------------
__device__ float g_gate[(size_t)M_SZ * C_SZ];
__device__ float g_val [(size_t)M_SZ * C_SZ];
__device__ __half g_a16[(size_t)M_SZ * K_SZ];          // x rounded to fp16
__device__ __half g_b16[(size_t)N_SZ * K_SZ];          // W rounded to fp16

// scan chunk summaries: 32 chunks x 8192 sequences
#define SCAN_CH 128
#define SCAN_NCH (T_SZ / SCAN_CH)   // 32
#define NSEQ (B_SZ * C_SZ)          // 8192
__device__ float g_Gc [SCAN_NCH * NSEQ];
__device__ float g_Vc [SCAN_NCH * NSEQ];
__device__ float g_Hin[SCAN_NCH * NSEQ];

// ---------------- helpers ----------------
__device__ __forceinline__ uint32_t smem_u32(const void* p) {
    uint32_t a;
    asm("{ .reg .u64 t; cvta.to.shared.u64 t, %1; cvt.u32.u64 %0, t; }" : "=r"(a) : "l"(p));
    return a;
}
__device__ __forceinline__ void cp16(uint32_t dst, const void* src) {
    asm volatile("cp.async.cg.shared.global [%0], [%1], 16;" :: "r"(dst), "l"(src));
}
#define CP_COMMIT() asm volatile("cp.async.commit_group;" ::: "memory")
#define CP_WAITN(n) asm volatile("cp.async.wait_group %0;" :: "n"(n) : "memory")

#define LDSM4(r0, r1, r2, r3, addr) \
    asm volatile("ldmatrix.sync.aligned.m8n8.x4.shared.b16 {%0,%1,%2,%3}, [%4];" \
        : "=r"(r0), "=r"(r1), "=r"(r2), "=r"(r3) : "r"(addr))

// fp16 inputs, fp32 accumulate
#define MMA16816(d, a, b0, b1) \
    asm volatile("mma.sync.aligned.m16n8k16.row.col.f32.f16.f16.f32 " \
        "{%0,%1,%2,%3},{%4,%5,%6,%7},{%8,%9},{%0,%1,%2,%3};" \
        : "+f"((d)[0]), "+f"((d)[1]), "+f"((d)[2]), "+f"((d)[3]) \
        : "r"((a)[0]), "r"((a)[1]), "r"((a)[2]), "r"((a)[3]), "r"(b0), "r"(b1))

__device__ __forceinline__ float act_sig(float v)  { return 1.0f / (1.0f + __expf(-v)); }
__device__ __forceinline__ float act_tanh(float v) { return 1.0f - 2.0f / (__expf(2.0f * v) + 1.0f); }

// ---------------- convert: x, W -> fp16 ----------------
__global__ __launch_bounds__(256) void convert_kernel(
    const float* __restrict__ x, const float* __restrict__ W)
{
    const size_t MK4 = (size_t)M_SZ * K_SZ / 4;
    const size_t NK4 = (size_t)N_SZ * K_SZ / 4;
    size_t i = (size_t)blockIdx.x * blockDim.x + threadIdx.x;
    if (i >= MK4 + NK4) return;

    const float4* src; uint2* dst; size_t j;
    if (i < MK4) { src = (const float4*)x; dst = (uint2*)g_a16; j = i; }
    else         { src = (const float4*)W; dst = (uint2*)g_b16; j = i - MK4; }

    float4 v = src[j];
    __half2 h01 = __floats2half2_rn(v.x, v.y);
    __half2 h23 = __floats2half2_rn(v.z, v.w);
    uint2 o;
    o.x = *(uint32_t*)&h01; o.y = *(uint32_t*)&h23;
    dst[j] = o;
}

// ---------------- HMMA GEMM: C = A * W^T (+bias), fused activation ----------------
// CTA tile 128x128, BK=32. 8 warps: 2(M) x 4(N), warp tile 64x32.
// smem per stage: 2 tiles (A16, B16), each 128 rows x 32 fp16, row stride 80B.
// 3-stage cp.async pipeline, 2 CTAs/SM.
#define LDSM_STRIDE 80
#define TILE_SM 10240            // 128 * 80
#define STAGE_SM (2 * TILE_SM)   // 20480
#define NSTAGE 3
#define GEMM_SMEM (NSTAGE * STAGE_SM) // 61440
#define KCHUNKS 64               // 2048 / 32

__global__ __launch_bounds__(256, 2) void gemm_mma(const float* __restrict__ bias)
{
    extern __shared__ char smem[];
    const uint32_t sb = smem_u32(smem);
    const int tid  = threadIdx.x;
    const int lane = tid & 31;
    const int wid  = tid >> 5;
    const int bx = blockIdx.x;   // N tile 0..31
    const int by = blockIdx.y;   // M tile 0..127

    const int m_off = (wid & 1) * 64;
    const int n_off = (wid >> 1) * 32;

    float acc[4][4][4];
#pragma unroll
    for (int mi = 0; mi < 4; mi++)
#pragma unroll
        for (int ni = 0; ni < 4; ni++)
#pragma unroll
            for (int u = 0; u < 4; u++) acc[mi][ni][u] = 0.0f;

    // ldmatrix per-lane address components
    const uint32_t a_off = (uint32_t)(m_off + (lane & 15)) * LDSM_STRIDE + ((lane >> 4) * 16);
    const uint32_t b_off = (uint32_t)(n_off + (lane & 7) + (((lane >> 3) >> 1) * 8)) * LDSM_STRIDE
                           + (((lane >> 3) & 1) * 16);

    // cp.async mapping: per tile, thread does ops o = 2*tid, 2*tid+1; row = o>>2, seg = o&3
    const int o0   = 2 * tid;
    const int rowL = o0 >> 2;            // 0..127
    const int segL = o0 & 3;             // 0 or 2 (i adds 0/1)

    auto load_stage = [&](int st, int c) {
        const uint32_t base = sb + st * STAGE_SM;
#pragma unroll
        for (int i = 0; i < 2; i++) {
            const int row = rowL;
            const int seg = segL + i;
            const size_t gA = (size_t)(by * 128 + row) * K_SZ + c * 32 + seg * 8;
            const size_t gB = (size_t)(bx * 128 + row) * K_SZ + c * 32 + seg * 8;
            const uint32_t so = base + (uint32_t)row * LDSM_STRIDE + seg * 16;
            cp16(so,           g_a16 + gA);
            cp16(so + TILE_SM, g_b16 + gB);
        }
    };

    auto compute = [&](int st) {
        const uint32_t base = sb + st * STAGE_SM;
#pragma unroll
        for (int s = 0; s < 2; s++) {
            const uint32_t ks = s * 32;                        // 16 fp16 = 32B per k16 step
            const uint32_t aB = base + a_off + ks;             // A tile
            const uint32_t bB = base + TILE_SM + b_off + ks;   // B tile
            uint32_t a[16], b[8];
#pragma unroll
            for (int mi = 0; mi < 4; mi++)
                LDSM4(a[mi*4+0], a[mi*4+1], a[mi*4+2], a[mi*4+3], aB + mi * 16 * LDSM_STRIDE);
#pragma unroll
            for (int nj = 0; nj < 2; nj++)
                LDSM4(b[nj*4+0], b[nj*4+1], b[nj*4+2], b[nj*4+3], bB + nj * 16 * LDSM_STRIDE);
#pragma unroll
            for (int mi = 0; mi < 4; mi++)
#pragma unroll
                for (int ni = 0; ni < 4; ni++)
                    MMA16816(acc[mi][ni], &a[mi*4], b[(ni>>1)*4 + (ni&1)*2], b[(ni>>1)*4 + (ni&1)*2 + 1]);
        }
    };

    // ---- 3-stage pipelined main loop ----
    load_stage(0, 0); CP_COMMIT();
    load_stage(1, 1); CP_COMMIT();
    int st = 0;
    for (int c = 0; c < KCHUNKS; c++) {
        if (c + 2 < KCHUNKS) {
            load_stage((st + 2) % NSTAGE, c + 2); CP_COMMIT();
            CP_WAITN(2);
        } else if (c + 1 < KCHUNKS) {
            CP_WAITN(1);
        } else {
            CP_WAITN(0);
        }
        __syncthreads();
        compute(st);
        __syncthreads();
        st = (st + 1) % NSTAGE;
    }

    // ---- epilogue: bias + activation -> g_gate / g_val ----
    const int n0 = bx * 128;
    const bool is_gate = (bx < 16);
    float* dst = is_gate ? g_gate : g_val;
    const int cadj = is_gate ? 0 : C_SZ;
    const int r_in  = lane >> 2;
    const int cpair = (lane & 3) * 2;

#pragma unroll
    for (int mi = 0; mi < 4; mi++) {
        const int gm = by * 128 + m_off + mi * 16 + r_in;
        float* row0 = dst + (size_t)gm * C_SZ + (n0 - cadj);
        float* row1 = row0 + (size_t)8 * C_SZ;
#pragma unroll
        for (int ni = 0; ni < 4; ni++) {
            const int col = n_off + ni * 8 + cpair;
            const float b0 = __ldg(bias + n0 + col);
            const float b1 = __ldg(bias + n0 + col + 1);
            float v0 = acc[mi][ni][0] + b0, v1 = acc[mi][ni][1] + b1;
            float v2 = acc[mi][ni][2] + b0, v3 = acc[mi][ni][3] + b1;
            float o0, o1, o2, o3;
            if (is_gate) { o0 = act_sig(v0);  o1 = act_sig(v1);  o2 = act_sig(v2);  o3 = act_sig(v3); }
            else         { o0 = act_tanh(v0); o1 = act_tanh(v1); o2 = act_tanh(v2); o3 = act_tanh(v3); }
            *(float2*)(row0 + col) = make_float2(o0, o1);
            *(float2*)(row1 + col) = make_float2(o2, o3);
        }
    }
}

// ---------------- chunked scan: 3 passes ----------------
__global__ __launch_bounds__(256) void scan_pass1()
{
    const int id = blockIdx.x * blockDim.x + threadIdx.x;
    if (id >= NSEQ * SCAN_NCH) return;
    const int chunk = id / NSEQ;
    const int s     = id - chunk * NSEQ;
    const int bb = s >> 11;
    const int c  = s & 2047;
    const size_t base = (size_t)bb * T_SZ * C_SZ + (size_t)chunk * SCAN_CH * C_SZ + c;

    const float* gp = g_gate + base;
    const float* vp = g_val  + base;

    float G = 1.0f, V = 0.0f;
#pragma unroll 1
    for (int t = 0; t < SCAN_CH; t += 8) {
        float g[8], v[8];
#pragma unroll
        for (int u = 0; u < 8; u++) {
            g[u] = __ldg(gp + (size_t)(t + u) * C_SZ);
            v[u] = __ldg(vp + (size_t)(t + u) * C_SZ);
        }
#pragma unroll
        for (int u = 0; u < 8; u++) {
            V = fmaf(g[u], V, v[u]);
            G *= g[u];
        }
    }
    g_Gc[chunk * NSEQ + s] = G;
    g_Vc[chunk * NSEQ + s] = V;
}

__global__ __launch_bounds__(256) void scan_pass2()
{
    const int s = blockIdx.x * blockDim.x + threadIdx.x;
    if (s >= NSEQ) return;
    float h = 0.0f;
#pragma unroll
    for (int j = 0; j < SCAN_NCH; j++) {
        g_Hin[j * NSEQ + s] = h;
        h = fmaf(g_Gc[j * NSEQ + s], h, g_Vc[j * NSEQ + s]);
    }
}

__global__ __launch_bounds__(256) void scan_pass3(float* __restrict__ out)
{
    const int id = blockIdx.x * blockDim.x + threadIdx.x;
    if (id >= NSEQ * SCAN_NCH) return;
    const int chunk = id / NSEQ;
    const int s     = id - chunk * NSEQ;
    const int bb = s >> 11;
    const int c  = s & 2047;
    const size_t base = (size_t)bb * T_SZ * C_SZ + (size_t)chunk * SCAN_CH * C_SZ + c;

    const float* gp = g_gate + base;
    const float* vp = g_val  + base;
    float*       op = out    + base;

    float h = g_Hin[chunk * NSEQ + s];
#pragma unroll 1
    for (int t = 0; t < SCAN_CH; t += 8) {
        float g[8], v[8];
#pragma unroll
        for (int u = 0; u < 8; u++) {
            g[u] = __ldg(gp + (size_t)(t + u) * C_SZ);
            v[u] = __ldg(vp + (size_t)(t + u) * C_SZ);
        }
#pragma unroll
        for (int u = 0; u < 8; u++) {
            h = fmaf(g[u], h, v[u]);
            op[(size_t)(t + u) * C_SZ] = h;
        }
    }
}

// ---------------- launch ----------------
extern "C" void kernel_launch(void* const* d_in, const int* in_sizes, int n_in,
                              void* d_out, int out_size)
{
    const float* x  = (const float*)d_in[0];  // [B,T,C]
    const float* W  = (const float*)d_in[1];  // [2C,C]
    const float* bi = (const float*)d_in[2];  // [2C]
    float* out = (float*)d_out;               // [B,T,C]

    cudaFuncSetAttribute(gemm_mma, cudaFuncAttributeMaxDynamicSharedMemorySize, GEMM_SMEM);

    const size_t total4 = ((size_t)M_SZ * K_SZ + (size_t)N_SZ * K_SZ) / 4;
    convert_kernel<<<(unsigned)((total4 + 255) / 256), 256>>>(x, W);

    gemm_mma<<<dim3(32, 128), 256, GEMM_SMEM>>>(bi);

    const int nwork = NSEQ * SCAN_NCH;       // 262144
    scan_pass1<<<(nwork + 255) / 256, 256>>>();
    scan_pass2<<<(NSEQ + 255) / 256, 256>>>();
    scan_pass3<<<(nwork + 255) / 256, 256>>>(out);
}

// round 9
// speedup vs baseline: 4.5109x; 1.0736x over previous
#include <cuda_runtime.h>
#include <cuda_fp16.h>
#include <cstdint>
#include <math.h>

// ---------------- problem shapes ----------------
#define B_SZ 4
#define T_SZ 4096
#define C_SZ 2048
#define M_SZ (B_SZ * T_SZ)   // 16384
#define N_SZ (2 * C_SZ)      // 4096
#define K_SZ C_SZ            // 2048

// ---------------- device scratch ----------------
__device__ float g_gate[(size_t)M_SZ * C_SZ];
__device__ float g_val [(size_t)M_SZ * C_SZ];
__device__ __half g_a16[(size_t)M_SZ * K_SZ];          // x rounded to fp16
__device__ __half g_b16[(size_t)N_SZ * K_SZ];          // W rounded to fp16

// scan chunk summaries: 32 chunks x 8192 sequences
#define SCAN_CH 128
#define SCAN_NCH (T_SZ / SCAN_CH)   // 32
#define NSEQ (B_SZ * C_SZ)          // 8192
__device__ float g_Gc [SCAN_NCH * NSEQ];
__device__ float g_Vc [SCAN_NCH * NSEQ];
__device__ float g_Hin[SCAN_NCH * NSEQ];

// ---------------- helpers ----------------
__device__ __forceinline__ uint32_t smem_u32(const void* p) {
    uint32_t a;
    asm("{ .reg .u64 t; cvta.to.shared.u64 t, %1; cvt.u32.u64 %0, t; }" : "=r"(a) : "l"(p));
    return a;
}
__device__ __forceinline__ void cp16(uint32_t dst, const void* src) {
    asm volatile("cp.async.cg.shared.global [%0], [%1], 16;" :: "r"(dst), "l"(src));
}
#define CP_COMMIT() asm volatile("cp.async.commit_group;" ::: "memory")
#define CP_WAITN(n) asm volatile("cp.async.wait_group %0;" :: "n"(n) : "memory")

#define LDSM4(r0, r1, r2, r3, addr) \
    asm volatile("ldmatrix.sync.aligned.m8n8.x4.shared.b16 {%0,%1,%2,%3}, [%4];" \
        : "=r"(r0), "=r"(r1), "=r"(r2), "=r"(r3) : "r"(addr))

// fp16 inputs, fp32 accumulate
#define MMA16816(d, a, b0, b1) \
    asm volatile("mma.sync.aligned.m16n8k16.row.col.f32.f16.f16.f32 " \
        "{%0,%1,%2,%3},{%4,%5,%6,%7},{%8,%9},{%0,%1,%2,%3};" \
        : "+f"((d)[0]), "+f"((d)[1]), "+f"((d)[2]), "+f"((d)[3]) \
        : "r"((a)[0]), "r"((a)[1]), "r"((a)[2]), "r"((a)[3]), "r"(b0), "r"(b1))

__device__ __forceinline__ float act_sig(float v)  { return 1.0f / (1.0f + __expf(-v)); }
__device__ __forceinline__ float act_tanh(float v) { return 1.0f - 2.0f / (__expf(2.0f * v) + 1.0f); }

// ---------------- convert: x, W -> fp16 ----------------
__global__ __launch_bounds__(256) void convert_kernel(
    const float* __restrict__ x, const float* __restrict__ W)
{
    const size_t MK4 = (size_t)M_SZ * K_SZ / 4;
    const size_t NK4 = (size_t)N_SZ * K_SZ / 4;
    size_t i = (size_t)blockIdx.x * blockDim.x + threadIdx.x;
    if (i >= MK4 + NK4) return;

    const float4* src; uint2* dst; size_t j;
    if (i < MK4) { src = (const float4*)x; dst = (uint2*)g_a16; j = i; }
    else         { src = (const float4*)W; dst = (uint2*)g_b16; j = i - MK4; }

    float4 v = src[j];
    __half2 h01 = __floats2half2_rn(v.x, v.y);
    __half2 h23 = __floats2half2_rn(v.z, v.w);
    uint2 o;
    o.x = *(uint32_t*)&h01; o.y = *(uint32_t*)&h23;
    dst[j] = o;
}

// ---------------- HMMA GEMM: C = A * W^T (+bias), fused activation ----------------
// CTA tile 128x128, BK=32. 8 warps: 2(M) x 4(N), warp tile 64x32.
// smem per stage: 2 tiles (A16, B16), each 128 rows x 32 fp16, row stride 80B.
// 4-stage cp.async pipeline, ONE barrier per chunk, 2 CTAs/SM.
#define LDSM_STRIDE 80
#define TILE_SM 10240            // 128 * 80
#define STAGE_SM (2 * TILE_SM)   // 20480
#define NSTAGE 4
#define GEMM_SMEM (NSTAGE * STAGE_SM) // 81920
#define KCHUNKS 64               // 2048 / 32

__global__ __launch_bounds__(256, 2) void gemm_mma(const float* __restrict__ bias)
{
    extern __shared__ char smem[];
    const uint32_t sb = smem_u32(smem);
    const int tid  = threadIdx.x;
    const int lane = tid & 31;
    const int wid  = tid >> 5;
    const int bx = blockIdx.x;   // N tile 0..31
    const int by = blockIdx.y;   // M tile 0..127

    const int m_off = (wid & 1) * 64;
    const int n_off = (wid >> 1) * 32;

    float acc[4][4][4];
#pragma unroll
    for (int mi = 0; mi < 4; mi++)
#pragma unroll
        for (int ni = 0; ni < 4; ni++)
#pragma unroll
            for (int u = 0; u < 4; u++) acc[mi][ni][u] = 0.0f;

    // ldmatrix per-lane address components
    const uint32_t a_off = (uint32_t)(m_off + (lane & 15)) * LDSM_STRIDE + ((lane >> 4) * 16);
    const uint32_t b_off = (uint32_t)(n_off + (lane & 7) + (((lane >> 3) >> 1) * 8)) * LDSM_STRIDE
                           + (((lane >> 3) & 1) * 16);

    // cp.async mapping: per tile, thread does ops o = 2*tid, 2*tid+1; row = o>>2, seg = o&3
    const int o0   = 2 * tid;
    const int rowL = o0 >> 2;            // 0..127
    const int segL = o0 & 3;             // 0 or 2 (i adds 0/1)

    auto load_stage = [&](int st, int c) {
        const uint32_t base = sb + st * STAGE_SM;
#pragma unroll
        for (int i = 0; i < 2; i++) {
            const int row = rowL;
            const int seg = segL + i;
            const size_t gA = (size_t)(by * 128 + row) * K_SZ + c * 32 + seg * 8;
            const size_t gB = (size_t)(bx * 128 + row) * K_SZ + c * 32 + seg * 8;
            const uint32_t so = base + (uint32_t)row * LDSM_STRIDE + seg * 16;
            cp16(so,           g_a16 + gA);
            cp16(so + TILE_SM, g_b16 + gB);
        }
    };

    auto compute = [&](int st) {
        const uint32_t base = sb + st * STAGE_SM;
#pragma unroll
        for (int s = 0; s < 2; s++) {
            const uint32_t ks = s * 32;                        // 16 fp16 = 32B per k16 step
            const uint32_t aB = base + a_off + ks;             // A tile
            const uint32_t bB = base + TILE_SM + b_off + ks;   // B tile
            uint32_t a[16], b[8];
#pragma unroll
            for (int nj = 0; nj < 2; nj++)
                LDSM4(b[nj*4+0], b[nj*4+1], b[nj*4+2], b[nj*4+3], bB + nj * 16 * LDSM_STRIDE);
#pragma unroll
            for (int mi = 0; mi < 4; mi++)
                LDSM4(a[mi*4+0], a[mi*4+1], a[mi*4+2], a[mi*4+3], aB + mi * 16 * LDSM_STRIDE);
#pragma unroll
            for (int mi = 0; mi < 4; mi++)
#pragma unroll
                for (int ni = 0; ni < 4; ni++)
                    MMA16816(acc[mi][ni], &a[mi*4], b[(ni>>1)*4 + (ni&1)*2], b[(ni>>1)*4 + (ni&1)*2 + 1]);
        }
    };

    // ---- 4-stage pipelined main loop, single barrier per chunk ----
    load_stage(0, 0); CP_COMMIT();
    load_stage(1, 1); CP_COMMIT();
    load_stage(2, 2); CP_COMMIT();
    int st = 0;
    for (int c = 0; c < KCHUNKS; c++) {
        if (c + 2 < KCHUNKS)      { CP_WAITN(2); }
        else if (c + 1 < KCHUNKS) { CP_WAITN(1); }
        else                      { CP_WAITN(0); }
        // Barrier: every warp passing here has finished compute(c-1), whose
        // stage (c-1)%4 == (c+3)%4 is exactly the stage we overwrite below.
        __syncthreads();
        if (c + 3 < KCHUNKS) { load_stage((st + 3) & 3, c + 3); CP_COMMIT(); }
        compute(st);
        st = (st + 1) & 3;
    }

    // ---- epilogue: bias + activation -> g_gate / g_val ----
    const int n0 = bx * 128;
    const bool is_gate = (bx < 16);
    float* dst = is_gate ? g_gate : g_val;
    const int cadj = is_gate ? 0 : C_SZ;
    const int r_in  = lane >> 2;
    const int cpair = (lane & 3) * 2;

    float bb0[4], bb1[4];
#pragma unroll
    for (int ni = 0; ni < 4; ni++) {
        const int col = n_off + ni * 8 + cpair;
        bb0[ni] = __ldg(bias + n0 + col);
        bb1[ni] = __ldg(bias + n0 + col + 1);
    }

#pragma unroll
    for (int mi = 0; mi < 4; mi++) {
        const int gm = by * 128 + m_off + mi * 16 + r_in;
        float* row0 = dst + (size_t)gm * C_SZ + (n0 - cadj);
        float* row1 = row0 + (size_t)8 * C_SZ;
#pragma unroll
        for (int ni = 0; ni < 4; ni++) {
            const int col = n_off + ni * 8 + cpair;
            float v0 = acc[mi][ni][0] + bb0[ni], v1 = acc[mi][ni][1] + bb1[ni];
            float v2 = acc[mi][ni][2] + bb0[ni], v3 = acc[mi][ni][3] + bb1[ni];
            float o0, o1, o2, o3;
            if (is_gate) { o0 = act_sig(v0);  o1 = act_sig(v1);  o2 = act_sig(v2);  o3 = act_sig(v3); }
            else         { o0 = act_tanh(v0); o1 = act_tanh(v1); o2 = act_tanh(v2); o3 = act_tanh(v3); }
            *(float2*)(row0 + col) = make_float2(o0, o1);
            *(float2*)(row1 + col) = make_float2(o2, o3);
        }
    }
}

// ---------------- chunked scan: 3 passes ----------------
__global__ __launch_bounds__(256) void scan_pass1()
{
    const int id = blockIdx.x * blockDim.x + threadIdx.x;
    if (id >= NSEQ * SCAN_NCH) return;
    const int chunk = id / NSEQ;
    const int s     = id - chunk * NSEQ;
    const int bb = s >> 11;
    const int c  = s & 2047;
    const size_t base = (size_t)bb * T_SZ * C_SZ + (size_t)chunk * SCAN_CH * C_SZ + c;

    const float* gp = g_gate + base;
    const float* vp = g_val  + base;

    float G = 1.0f, V = 0.0f;
#pragma unroll 1
    for (int t = 0; t < SCAN_CH; t += 16) {
        float g[16], v[16];
#pragma unroll
        for (int u = 0; u < 16; u++) {
            g[u] = __ldg(gp + (size_t)(t + u) * C_SZ);
            v[u] = __ldg(vp + (size_t)(t + u) * C_SZ);
        }
#pragma unroll
        for (int u = 0; u < 16; u++) {
            V = fmaf(g[u], V, v[u]);
            G *= g[u];
        }
    }
    g_Gc[chunk * NSEQ + s] = G;
    g_Vc[chunk * NSEQ + s] = V;
}

// pass2: prefetch all chunk summaries (independent loads, full MLP), then scan
__global__ __launch_bounds__(256) void scan_pass2()
{
    const int s = blockIdx.x * blockDim.x + threadIdx.x;
    if (s >= NSEQ) return;
    float G[SCAN_NCH], V[SCAN_NCH];
#pragma unroll
    for (int j = 0; j < SCAN_NCH; j++) {
        G[j] = __ldg(&g_Gc[j * NSEQ + s]);
        V[j] = __ldg(&g_Vc[j * NSEQ + s]);
    }
    float h = 0.0f;
#pragma unroll
    for (int j = 0; j < SCAN_NCH; j++) {
        g_Hin[j * NSEQ + s] = h;
        h = fmaf(G[j], h, V[j]);
    }
}

__global__ __launch_bounds__(256) void scan_pass3(float* __restrict__ out)
{
    const int id = blockIdx.x * blockDim.x + threadIdx.x;
    if (id >= NSEQ * SCAN_NCH) return;
    const int chunk = id / NSEQ;
    const int s     = id - chunk * NSEQ;
    const int bb = s >> 11;
    const int c  = s & 2047;
    const size_t base = (size_t)bb * T_SZ * C_SZ + (size_t)chunk * SCAN_CH * C_SZ + c;

    const float* gp = g_gate + base;
    const float* vp = g_val  + base;
    float*       op = out    + base;

    float h = g_Hin[chunk * NSEQ + s];
#pragma unroll 1
    for (int t = 0; t < SCAN_CH; t += 16) {
        float g[16], v[16];
#pragma unroll
        for (int u = 0; u < 16; u++) {
            g[u] = __ldg(gp + (size_t)(t + u) * C_SZ);
            v[u] = __ldg(vp + (size_t)(t + u) * C_SZ);
        }
#pragma unroll
        for (int u = 0; u < 16; u++) {
            h = fmaf(g[u], h, v[u]);
            op[(size_t)(t + u) * C_SZ] = h;
        }
    }
}

// ---------------- launch ----------------
extern "C" void kernel_launch(void* const* d_in, const int* in_sizes, int n_in,
                              void* d_out, int out_size)
{
    const float* x  = (const float*)d_in[0];  // [B,T,C]
    const float* W  = (const float*)d_in[1];  // [2C,C]
    const float* bi = (const float*)d_in[2];  // [2C]
    float* out = (float*)d_out;               // [B,T,C]

    cudaFuncSetAttribute(gemm_mma, cudaFuncAttributeMaxDynamicSharedMemorySize, GEMM_SMEM);

    const size_t total4 = ((size_t)M_SZ * K_SZ + (size_t)N_SZ * K_SZ) / 4;
    convert_kernel<<<(unsigned)((total4 + 255) / 256), 256>>>(x, W);

    gemm_mma<<<dim3(32, 128), 256, GEMM_SMEM>>>(bi);

    const int nwork = NSEQ * SCAN_NCH;       // 262144
    scan_pass1<<<(nwork + 255) / 256, 256>>>();
    scan_pass2<<<(NSEQ + 255) / 256, 256>>>();
    scan_pass3<<<(nwork + 255) / 256, 256>>>(out);
}

// round 10
// speedup vs baseline: 4.6558x; 1.0321x over previous
#include <cuda_runtime.h>
#include <cuda_fp16.h>
#include <cstdint>
#include <math.h>

// ---------------- problem shapes ----------------
#define B_SZ 4
#define T_SZ 4096
#define C_SZ 2048
#define M_SZ (B_SZ * T_SZ)   // 16384
#define N_SZ (2 * C_SZ)      // 4096
#define K_SZ C_SZ            // 2048

// ---------------- device scratch ----------------
__device__ __half g_gate16[(size_t)M_SZ * C_SZ];
__device__ __half g_val16 [(size_t)M_SZ * C_SZ];
__device__ __half g_a16[(size_t)M_SZ * K_SZ];          // x rounded to fp16
__device__ __half g_b16[(size_t)N_SZ * K_SZ];          // W rounded to fp16

// scan chunk summaries: 32 chunks x 8192 sequences (fp32 for precision)
#define SCAN_CH 128
#define SCAN_NCH (T_SZ / SCAN_CH)   // 32
#define NSEQ (B_SZ * C_SZ)          // 8192
#define NSEQ2 (NSEQ / 2)            // 4096 channel-pairs
__device__ float g_Gc [SCAN_NCH * NSEQ];
__device__ float g_Vc [SCAN_NCH * NSEQ];
__device__ float g_Hin[SCAN_NCH * NSEQ];

// ---------------- helpers ----------------
__device__ __forceinline__ uint32_t smem_u32(const void* p) {
    uint32_t a;
    asm("{ .reg .u64 t; cvta.to.shared.u64 t, %1; cvt.u32.u64 %0, t; }" : "=r"(a) : "l"(p));
    return a;
}
__device__ __forceinline__ void cp16(uint32_t dst, const void* src) {
    asm volatile("cp.async.cg.shared.global [%0], [%1], 16;" :: "r"(dst), "l"(src));
}
#define CP_COMMIT() asm volatile("cp.async.commit_group;" ::: "memory")
#define CP_WAITN(n) asm volatile("cp.async.wait_group %0;" :: "n"(n) : "memory")

#define LDSM4(r0, r1, r2, r3, addr) \
    asm volatile("ldmatrix.sync.aligned.m8n8.x4.shared.b16 {%0,%1,%2,%3}, [%4];" \
        : "=r"(r0), "=r"(r1), "=r"(r2), "=r"(r3) : "r"(addr))

// fp16 inputs, fp32 accumulate
#define MMA16816(d, a, b0, b1) \
    asm volatile("mma.sync.aligned.m16n8k16.row.col.f32.f16.f16.f32 " \
        "{%0,%1,%2,%3},{%4,%5,%6,%7},{%8,%9},{%0,%1,%2,%3};" \
        : "+f"((d)[0]), "+f"((d)[1]), "+f"((d)[2]), "+f"((d)[3]) \
        : "r"((a)[0]), "r"((a)[1]), "r"((a)[2]), "r"((a)[3]), "r"(b0), "r"(b1))

__device__ __forceinline__ float act_sig(float v)  { return 1.0f / (1.0f + __expf(-v)); }
__device__ __forceinline__ float act_tanh(float v) { return 1.0f - 2.0f / (__expf(2.0f * v) + 1.0f); }

// ---------------- convert: x, W -> fp16 ----------------
__global__ __launch_bounds__(256) void convert_kernel(
    const float* __restrict__ x, const float* __restrict__ W)
{
    const size_t MK4 = (size_t)M_SZ * K_SZ / 4;
    const size_t NK4 = (size_t)N_SZ * K_SZ / 4;
    size_t i = (size_t)blockIdx.x * blockDim.x + threadIdx.x;
    if (i >= MK4 + NK4) return;

    const float4* src; uint2* dst; size_t j;
    if (i < MK4) { src = (const float4*)x; dst = (uint2*)g_a16; j = i; }
    else         { src = (const float4*)W; dst = (uint2*)g_b16; j = i - MK4; }

    float4 v = src[j];
    __half2 h01 = __floats2half2_rn(v.x, v.y);
    __half2 h23 = __floats2half2_rn(v.z, v.w);
    uint2 o;
    o.x = *(uint32_t*)&h01; o.y = *(uint32_t*)&h23;
    dst[j] = o;
}

// ---------------- HMMA GEMM: C = A * W^T (+bias), fused activation ----------------
// CTA tile 128x128, BK=32. 8 warps: 2(M) x 4(N), warp tile 64x32.
// 4-stage cp.async pipeline, ONE barrier per chunk, 2 CTAs/SM.
#define LDSM_STRIDE 80
#define TILE_SM 10240            // 128 * 80
#define STAGE_SM (2 * TILE_SM)   // 20480
#define NSTAGE 4
#define GEMM_SMEM (NSTAGE * STAGE_SM) // 81920
#define KCHUNKS 64               // 2048 / 32

__global__ __launch_bounds__(256, 2) void gemm_mma(const float* __restrict__ bias)
{
    extern __shared__ char smem[];
    const uint32_t sb = smem_u32(smem);
    const int tid  = threadIdx.x;
    const int lane = tid & 31;
    const int wid  = tid >> 5;
    const int bx = blockIdx.x;   // N tile 0..31
    const int by = blockIdx.y;   // M tile 0..127

    const int m_off = (wid & 1) * 64;
    const int n_off = (wid >> 1) * 32;

    float acc[4][4][4];
#pragma unroll
    for (int mi = 0; mi < 4; mi++)
#pragma unroll
        for (int ni = 0; ni < 4; ni++)
#pragma unroll
            for (int u = 0; u < 4; u++) acc[mi][ni][u] = 0.0f;

    const uint32_t a_off = (uint32_t)(m_off + (lane & 15)) * LDSM_STRIDE + ((lane >> 4) * 16);
    const uint32_t b_off = (uint32_t)(n_off + (lane & 7) + (((lane >> 3) >> 1) * 8)) * LDSM_STRIDE
                           + (((lane >> 3) & 1) * 16);

    const int o0   = 2 * tid;
    const int rowL = o0 >> 2;            // 0..127
    const int segL = o0 & 3;             // 0 or 2 (i adds 0/1)

    auto load_stage = [&](int st, int c) {
        const uint32_t base = sb + st * STAGE_SM;
#pragma unroll
        for (int i = 0; i < 2; i++) {
            const int row = rowL;
            const int seg = segL + i;
            const size_t gA = (size_t)(by * 128 + row) * K_SZ + c * 32 + seg * 8;
            const size_t gB = (size_t)(bx * 128 + row) * K_SZ + c * 32 + seg * 8;
            const uint32_t so = base + (uint32_t)row * LDSM_STRIDE + seg * 16;
            cp16(so,           g_a16 + gA);
            cp16(so + TILE_SM, g_b16 + gB);
        }
    };

    auto compute = [&](int st) {
        const uint32_t base = sb + st * STAGE_SM;
#pragma unroll
        for (int s = 0; s < 2; s++) {
            const uint32_t ks = s * 32;
            const uint32_t aB = base + a_off + ks;
            const uint32_t bB = base + TILE_SM + b_off + ks;
            uint32_t a[16], b[8];
#pragma unroll
            for (int nj = 0; nj < 2; nj++)
                LDSM4(b[nj*4+0], b[nj*4+1], b[nj*4+2], b[nj*4+3], bB + nj * 16 * LDSM_STRIDE);
#pragma unroll
            for (int mi = 0; mi < 4; mi++)
                LDSM4(a[mi*4+0], a[mi*4+1], a[mi*4+2], a[mi*4+3], aB + mi * 16 * LDSM_STRIDE);
#pragma unroll
            for (int mi = 0; mi < 4; mi++)
#pragma unroll
                for (int ni = 0; ni < 4; ni++)
                    MMA16816(acc[mi][ni], &a[mi*4], b[(ni>>1)*4 + (ni&1)*2], b[(ni>>1)*4 + (ni&1)*2 + 1]);
        }
    };

    // ---- 4-stage pipelined main loop, single barrier per chunk ----
    load_stage(0, 0); CP_COMMIT();
    load_stage(1, 1); CP_COMMIT();
    load_stage(2, 2); CP_COMMIT();
    int st = 0;
    for (int c = 0; c < KCHUNKS; c++) {
        if (c + 2 < KCHUNKS)      { CP_WAITN(2); }
        else if (c + 1 < KCHUNKS) { CP_WAITN(1); }
        else                      { CP_WAITN(0); }
        __syncthreads();
        if (c + 3 < KCHUNKS) { load_stage((st + 3) & 3, c + 3); CP_COMMIT(); }
        compute(st);
        st = (st + 1) & 3;
    }

    // ---- epilogue: bias + activation -> fp16 g_gate16 / g_val16 ----
    const int n0 = bx * 128;
    const bool is_gate = (bx < 16);
    __half* dst = is_gate ? g_gate16 : g_val16;
    const int cadj = is_gate ? 0 : C_SZ;
    const int r_in  = lane >> 2;
    const int cpair = (lane & 3) * 2;

    float bb0[4], bb1[4];
#pragma unroll
    for (int ni = 0; ni < 4; ni++) {
        const int col = n_off + ni * 8 + cpair;
        bb0[ni] = __ldg(bias + n0 + col);
        bb1[ni] = __ldg(bias + n0 + col + 1);
    }

#pragma unroll
    for (int mi = 0; mi < 4; mi++) {
        const int gm = by * 128 + m_off + mi * 16 + r_in;
        __half* row0 = dst + (size_t)gm * C_SZ + (n0 - cadj);
        __half* row1 = row0 + (size_t)8 * C_SZ;
#pragma unroll
        for (int ni = 0; ni < 4; ni++) {
            const int col = n_off + ni * 8 + cpair;
            float v0 = acc[mi][ni][0] + bb0[ni], v1 = acc[mi][ni][1] + bb1[ni];
            float v2 = acc[mi][ni][2] + bb0[ni], v3 = acc[mi][ni][3] + bb1[ni];
            float o0, o1, o2, o3;
            if (is_gate) { o0 = act_sig(v0);  o1 = act_sig(v1);  o2 = act_sig(v2);  o3 = act_sig(v3); }
            else         { o0 = act_tanh(v0); o1 = act_tanh(v1); o2 = act_tanh(v2); o3 = act_tanh(v3); }
            *(__half2*)(row0 + col) = __floats2half2_rn(o0, o1);
            *(__half2*)(row1 + col) = __floats2half2_rn(o2, o3);
        }
    }
}

// ---------------- chunked scan: 3 passes, 2 channels per thread ----------------
// pass1: per (chunk, channel-pair) compute G = prod(g), V = local scan end.
__global__ __launch_bounds__(256) void scan_pass1()
{
    const int id = blockIdx.x * blockDim.x + threadIdx.x;
    if (id >= NSEQ2 * SCAN_NCH) return;
    const int chunk = id / NSEQ2;
    const int p     = id - chunk * NSEQ2;    // pair index: seq s = 2p, 2p+1
    const int bb = p >> 10;                  // batch
    const int c  = (p & 1023) * 2;           // channel
    const size_t base = (size_t)bb * T_SZ * C_SZ + (size_t)chunk * SCAN_CH * C_SZ + c;

    const __half2* gp = (const __half2*)(g_gate16 + base);
    const __half2* vp = (const __half2*)(g_val16  + base);

    float2 G = make_float2(1.0f, 1.0f), V = make_float2(0.0f, 0.0f);
#pragma unroll 1
    for (int t = 0; t < SCAN_CH; t += 16) {
        __half2 g[16], v[16];
#pragma unroll
        for (int u = 0; u < 16; u++) {
            g[u] = __ldg(gp + (size_t)(t + u) * (C_SZ / 2));
            v[u] = __ldg(vp + (size_t)(t + u) * (C_SZ / 2));
        }
#pragma unroll
        for (int u = 0; u < 16; u++) {
            float2 gg = __half22float2(g[u]);
            float2 vv = __half22float2(v[u]);
            V.x = fmaf(gg.x, V.x, vv.x);
            V.y = fmaf(gg.y, V.y, vv.y);
            G.x *= gg.x;
            G.y *= gg.y;
        }
    }
    ((float2*)g_Gc)[chunk * NSEQ2 + p] = G;
    ((float2*)g_Vc)[chunk * NSEQ2 + p] = V;
}

// pass2: prefetch all chunk summaries (independent loads, full MLP), then scan
__global__ __launch_bounds__(256) void scan_pass2()
{
    const int s = blockIdx.x * blockDim.x + threadIdx.x;
    if (s >= NSEQ) return;
    float G[SCAN_NCH], V[SCAN_NCH];
#pragma unroll
    for (int j = 0; j < SCAN_NCH; j++) {
        G[j] = __ldg(&g_Gc[j * NSEQ + s]);
        V[j] = __ldg(&g_Vc[j * NSEQ + s]);
    }
    float h = 0.0f;
#pragma unroll
    for (int j = 0; j < SCAN_NCH; j++) {
        g_Hin[j * NSEQ + s] = h;
        h = fmaf(G[j], h, V[j]);
    }
}

// pass3: apply carry, write final h (fp32 out)
__global__ __launch_bounds__(256) void scan_pass3(float* __restrict__ out)
{
    const int id = blockIdx.x * blockDim.x + threadIdx.x;
    if (id >= NSEQ2 * SCAN_NCH) return;
    const int chunk = id / NSEQ2;
    const int p     = id - chunk * NSEQ2;
    const int bb = p >> 10;
    const int c  = (p & 1023) * 2;
    const size_t base = (size_t)bb * T_SZ * C_SZ + (size_t)chunk * SCAN_CH * C_SZ + c;

    const __half2* gp = (const __half2*)(g_gate16 + base);
    const __half2* vp = (const __half2*)(g_val16  + base);
    float*         op = out + base;

    float2 h = ((const float2*)g_Hin)[chunk * NSEQ2 + p];
#pragma unroll 1
    for (int t = 0; t < SCAN_CH; t += 16) {
        __half2 g[16], v[16];
#pragma unroll
        for (int u = 0; u < 16; u++) {
            g[u] = __ldg(gp + (size_t)(t + u) * (C_SZ / 2));
            v[u] = __ldg(vp + (size_t)(t + u) * (C_SZ / 2));
        }
#pragma unroll
        for (int u = 0; u < 16; u++) {
            float2 gg = __half22float2(g[u]);
            float2 vv = __half22float2(v[u]);
            h.x = fmaf(gg.x, h.x, vv.x);
            h.y = fmaf(gg.y, h.y, vv.y);
            *(float2*)(op + (size_t)(t + u) * C_SZ) = h;
        }
    }
}

// ---------------- launch ----------------
extern "C" void kernel_launch(void* const* d_in, const int* in_sizes, int n_in,
                              void* d_out, int out_size)
{
    const float* x  = (const float*)d_in[0];  // [B,T,C]
    const float* W  = (const float*)d_in[1];  // [2C,C]
    const float* bi = (const float*)d_in[2];  // [2C]
    float* out = (float*)d_out;               // [B,T,C]

    cudaFuncSetAttribute(gemm_mma, cudaFuncAttributeMaxDynamicSharedMemorySize, GEMM_SMEM);

    const size_t total4 = ((size_t)M_SZ * K_SZ + (size_t)N_SZ * K_SZ) / 4;
    convert_kernel<<<(unsigned)((total4 + 255) / 256), 256>>>(x, W);

    gemm_mma<<<dim3(32, 128), 256, GEMM_SMEM>>>(bi);

    const int nwork = NSEQ2 * SCAN_NCH;      // 131072
    scan_pass1<<<(nwork + 255) / 256, 256>>>();
    scan_pass2<<<(NSEQ + 255) / 256, 256>>>();
    scan_pass3<<<(nwork + 255) / 256, 256>>>(out);
}